// round 1
// baseline (speedup 1.0000x reference)
#include <cuda_runtime.h>
#include <cstdint>

#define NMETA 64
#define MSUB  1024
#define NNODE 65536
#define NEDGE 1048576
#define DH    128
#define DOUTD 64
#define NLAYER 3

// ---------------- scratch (static device globals; no allocation allowed) ----
__device__ float g_dinv[NNODE];
__device__ int   g_indeg[NNODE];
__device__ int   g_rowptr[NNODE + 1];
__device__ int   g_cursor[NNODE];
__device__ int   g_csr[NEDGE];
__device__ int   g_part[256];
__device__ float g_A[3][64 * 64];          // adj, adj^2, adj^3
__device__ float g_bsum[NLAYER][DH];
__device__ float g_H[(size_t)NNODE * 512]; // concat GEMM output [H0|H1|H2|H3]
__device__ float g_X[(size_t)NNODE * DH];
__device__ float g_S[(size_t)NNODE * DH];
__device__ float g_Z[(size_t)NNODE * DH];

// ---------------- graph preprocessing ---------------------------------------
__global__ void k_init() {
    int i = blockIdx.x * blockDim.x + threadIdx.x;
    if (i < NNODE) { g_indeg[i] = 0; g_cursor[i] = 0; }
}

__global__ void k_hist(const int* __restrict__ dst) {
    int e = blockIdx.x * blockDim.x + threadIdx.x;
    if (e < NEDGE) atomicAdd(&g_indeg[dst[e]], 1);
}

__global__ void k_scan_partial() {
    __shared__ int sh[256];
    int b = blockIdx.x, t = threadIdx.x;
    sh[t] = g_indeg[b * 256 + t];
    __syncthreads();
    for (int s = 128; s > 0; s >>= 1) {
        if (t < s) sh[t] += sh[t + s];
        __syncthreads();
    }
    if (t == 0) g_part[b] = sh[0];
}

__global__ void k_scan_block() {
    __shared__ int sh[256];
    int t = threadIdx.x;
    int v = g_part[t];
    sh[t] = v;
    __syncthreads();
    for (int off = 1; off < 256; off <<= 1) {
        int xv = (t >= off) ? sh[t - off] : 0;
        __syncthreads();
        sh[t] += xv;
        __syncthreads();
    }
    g_part[t] = sh[t] - v;   // exclusive
}

__global__ void k_scan_final() {
    __shared__ int sh[256];
    int b = blockIdx.x, t = threadIdx.x;
    int v = g_indeg[b * 256 + t];
    sh[t] = v;
    __syncthreads();
    for (int off = 1; off < 256; off <<= 1) {
        int xv = (t >= off) ? sh[t - off] : 0;
        __syncthreads();
        sh[t] += xv;
        __syncthreads();
    }
    int excl = sh[t] - v + g_part[b];
    g_rowptr[b * 256 + t] = excl;
    if (b == 255 && t == 255) g_rowptr[NNODE] = excl + v;
    g_dinv[b * 256 + t] = rsqrtf((float)(v + 1));   // +1 = self loop
}

__global__ void k_fill(const int* __restrict__ src, const int* __restrict__ dst) {
    int e = blockIdx.x * blockDim.x + threadIdx.x;
    if (e < NEDGE) {
        int d = dst[e];
        int p = atomicAdd(&g_cursor[d], 1);
        g_csr[g_rowptr[d] + p] = src[e];
    }
}

// ---------------- tiny meta-adjacency prep ----------------------------------
__global__ void k_copyA(const float* __restrict__ adj) {
    int i = blockIdx.x * blockDim.x + threadIdx.x;
    if (i < 4096) g_A[0][i] = adj[i];
}

__global__ void k_mm64(const float* __restrict__ A, const float* __restrict__ B,
                       float* __restrict__ C) {
    int c = threadIdx.x;
    for (int r = threadIdx.y; r < 64; r += blockDim.y) {
        float s = 0.f;
#pragma unroll 16
        for (int k = 0; k < 64; k++) s += A[r * 64 + k] * B[k * 64 + c];
        C[r * 64 + c] = s;
    }
}

__global__ void k_bsum(const float* __restrict__ gb) {
    int i = blockIdx.x * blockDim.x + threadIdx.x;
    if (i < NLAYER * DH) {
        int l = i / DH, c = i % DH;
        float s = 0.f;
        for (int j = 0; j < 4; j++) s += gb[(l * 4 + j) * DH + c];
        g_bsum[l][c] = s;
    }
}

// ---------------- GEMM: C[65536 x ncols] = X[65536 x 128] @ W[128 x wld] ----
// 64x64 block tile, 256 threads, 4x4 per thread, BK=16.
__global__ void __launch_bounds__(256) k_gemm(
    const float* __restrict__ X, const float* __restrict__ W, int wld,
    const float* __restrict__ bias, float* __restrict__ C,
    int ldc, int col0, int relu)
{
    __shared__ float As[16][64];
    __shared__ float Bs[16][68];
    int tid  = threadIdx.x;
    int row0 = blockIdx.y * 64;
    int n0   = blockIdx.x * 64;
    int lm = tid >> 2, lk = (tid & 3) * 4;
    int bk = tid >> 4, bn = (tid & 15) * 4;
    int tm = (tid >> 4) * 4, tn = (tid & 15) * 4;
    float acc[4][4] = {};
    for (int k0 = 0; k0 < 128; k0 += 16) {
        float4 av = *(const float4*)(X + (size_t)(row0 + lm) * 128 + k0 + lk);
        As[lk + 0][lm] = av.x; As[lk + 1][lm] = av.y;
        As[lk + 2][lm] = av.z; As[lk + 3][lm] = av.w;
        *(float4*)&Bs[bk][bn] = *(const float4*)(W + (size_t)(k0 + bk) * wld + n0 + bn);
        __syncthreads();
#pragma unroll
        for (int k = 0; k < 16; k++) {
            float4 a = *(const float4*)&As[k][tm];
            float4 b = *(const float4*)&Bs[k][tn];
            acc[0][0] += a.x * b.x; acc[0][1] += a.x * b.y; acc[0][2] += a.x * b.z; acc[0][3] += a.x * b.w;
            acc[1][0] += a.y * b.x; acc[1][1] += a.y * b.y; acc[1][2] += a.y * b.z; acc[1][3] += a.y * b.w;
            acc[2][0] += a.z * b.x; acc[2][1] += a.z * b.y; acc[2][2] += a.z * b.z; acc[2][3] += a.z * b.w;
            acc[3][0] += a.w * b.x; acc[3][1] += a.w * b.y; acc[3][2] += a.w * b.z; acc[3][3] += a.w * b.w;
        }
        __syncthreads();
    }
#pragma unroll
    for (int i = 0; i < 4; i++) {
        float4 o = make_float4(acc[i][0], acc[i][1], acc[i][2], acc[i][3]);
        if (bias) {
            o.x += bias[n0 + tn + 0]; o.y += bias[n0 + tn + 1];
            o.z += bias[n0 + tn + 2]; o.w += bias[n0 + tn + 3];
        }
        if (relu) {
            o.x = fmaxf(o.x, 0.f); o.y = fmaxf(o.y, 0.f);
            o.z = fmaxf(o.z, 0.f); o.w = fmaxf(o.w, 0.f);
        }
        *(float4*)(C + (size_t)(row0 + tm + i) * ldc + col0 + n0 + tn) = o;
    }
}

// ---------------- meta-mix: Z[v] = dinv[v]*(H0[v] + sum_{i,j} Ai[n,j]*Hi[j,m]) ----
// one block per m (1024 blocks), 128 threads = feature d; each thread holds all 64 n accs.
__global__ void __launch_bounds__(128) k_mix() {
    __shared__ float As[3][4096];  // As[i][j*64 + n] = A_i[n][j]  (transposed for broadcast)
    int t = threadIdx.x, m = blockIdx.x;
    for (int idx = t; idx < 3 * 4096; idx += 128) {
        int i = idx >> 12, rc = idx & 4095, n = rc >> 6, j = rc & 63;
        As[i][j * 64 + n] = g_A[i][n * 64 + j];
    }
    __syncthreads();
    float acc[64];
#pragma unroll
    for (int n = 0; n < 64; n++) acc[n] = 0.f;
    int d = t;
#pragma unroll 1
    for (int j = 0; j < 64; j++) {
        const float* hp = g_H + ((size_t)(j * 1024 + m)) * 512 + d;
        float h1 = hp[128], h2 = hp[256], h3 = hp[384];
        const float* a0 = &As[0][j * 64];
        const float* a1 = &As[1][j * 64];
        const float* a2 = &As[2][j * 64];
#pragma unroll
        for (int n = 0; n < 64; n++)
            acc[n] += a0[n] * h1 + a1[n] * h2 + a2[n] * h3;
    }
#pragma unroll 1
    for (int n = 0; n < 64; n++) {
        int v = n * 1024 + m;
        float y = g_H[(size_t)v * 512 + d] + acc[n];
        g_Z[(size_t)v * 128 + d] = g_dinv[v] * y;
    }
}

// ---------------- edge aggregation: out[v] = relu(dinv[v]*(Z[v]+sum Z[u]) + b) ----
__global__ void __launch_bounds__(256) k_agg(const float* __restrict__ Z,
                                             const float* __restrict__ bsum,
                                             float* __restrict__ out) {
    int w = (blockIdx.x * 256 + threadIdx.x) >> 5;
    int lane = threadIdx.x & 31;
    if (w >= NNODE) return;
    int v = w;
    float4 acc = *((const float4*)(Z + (size_t)v * 128) + lane);  // self loop term
    int p0 = g_rowptr[v], p1 = g_rowptr[v + 1];
    for (int p = p0; p < p1; p++) {
        int u = g_csr[p];
        float4 zu = *((const float4*)(Z + (size_t)u * 128) + lane);
        acc.x += zu.x; acc.y += zu.y; acc.z += zu.z; acc.w += zu.w;
    }
    float dv = g_dinv[v];
    float4 b = *((const float4*)bsum + lane);
    float4 o;
    o.x = fmaxf(dv * acc.x + b.x, 0.f);
    o.y = fmaxf(dv * acc.y + b.y, 0.f);
    o.z = fmaxf(dv * acc.z + b.z, 0.f);
    o.w = fmaxf(dv * acc.w + b.w, 0.f);
    *((float4*)(out + (size_t)v * 128) + lane) = o;
}

// ---------------- host orchestration ----------------------------------------
extern "C" void kernel_launch(void* const* d_in, const int* in_sizes, int n_in,
                              void* d_out, int out_size) {
    const float* x    = (const float*)d_in[0];
    const int*   sub  = (const int*)d_in[1];
    const float* adj  = (const float*)d_in[2];
    const float* gcnW = (const float*)d_in[3];
    const float* gcnB = (const float*)d_in[4];
    const float* W1   = (const float*)d_in[5];
    const float* b1   = (const float*)d_in[6];
    const float* W2   = (const float*)d_in[7];
    const float* b2   = (const float*)d_in[8];
    float* out = (float*)d_out;

    void* p;
    float *pH, *pX, *pS, *pZ, *pA, *pB;
    cudaGetSymbolAddress(&p, g_H);    pH = (float*)p;
    cudaGetSymbolAddress(&p, g_X);    pX = (float*)p;
    cudaGetSymbolAddress(&p, g_S);    pS = (float*)p;
    cudaGetSymbolAddress(&p, g_Z);    pZ = (float*)p;
    cudaGetSymbolAddress(&p, g_A);    pA = (float*)p;
    cudaGetSymbolAddress(&p, g_bsum); pB = (float*)p;

    // graph preprocessing (once per launch, reused by all layers)
    k_init<<<256, 256>>>();
    k_hist<<<NEDGE / 256, 256>>>(sub + NEDGE);
    k_scan_partial<<<256, 256>>>();
    k_scan_block<<<1, 256>>>();
    k_scan_final<<<256, 256>>>();
    k_fill<<<NEDGE / 256, 256>>>(sub, sub + NEDGE);

    // meta adjacency powers + summed biases
    k_copyA<<<16, 256>>>(adj);
    k_mm64<<<1, dim3(64, 16)>>>(pA, pA, pA + 4096);            // A^2
    k_mm64<<<1, dim3(64, 16)>>>(pA + 4096, pA, pA + 2 * 4096); // A^3
    k_bsum<<<2, 256>>>(gcnB);

    const float* cur = x;
    float* bufs[2] = { pX, pS };
    for (int l = 0; l < NLAYER; l++) {
        for (int i = 0; i < 4; i++) {
            k_gemm<<<dim3(2, NNODE / 64), 256>>>(
                cur, gcnW + (size_t)(l * 4 + i) * 128 * 128, 128,
                nullptr, pH, 512, i * 128, 0);
        }
        k_mix<<<1024, 128>>>();
        k_agg<<<NNODE / 8, 256>>>(pZ, pB + l * 128, bufs[l & 1]);
        cur = bufs[l & 1];
    }

    // MLP head: relu(x@W1+b1) @ W2 + b2
    k_gemm<<<dim3(2, NNODE / 64), 256>>>(cur, W1, 128, b1, pS, 128, 0, 1);
    k_gemm<<<dim3(1, NNODE / 64), 256>>>(pS, W2, 64, b2, out, 64, 0, 0);
}

// round 2
// speedup vs baseline: 2.0107x; 2.0107x over previous
#include <cuda_runtime.h>
#include <cstdint>

#define NNODE 65536
#define NEDGE 1048576
#define NLAYER 3

// ---------------- scratch (static device globals) ---------------------------
__device__ float g_dinv[NNODE];
__device__ int   g_indeg[NNODE];
__device__ int   g_rowptr[NNODE + 1];
__device__ int   g_cursor[NNODE];
__device__ int   g_csr[NEDGE];
__device__ int   g_part[256];
__device__ float g_A[3][64 * 64];              // [A, A^2, A^3] stacked: 192 x 64
__device__ float g_bsum[NLAYER][128];
__device__ float g_Y[(size_t)3 * NNODE * 128]; // mixed features (96 MB)
__device__ float g_X[(size_t)NNODE * 128];
__device__ float g_S[(size_t)NNODE * 128];
__device__ float g_Z[(size_t)NNODE * 128];

// ---------------- graph preprocessing ---------------------------------------
__global__ void k_init() {
    int i = blockIdx.x * blockDim.x + threadIdx.x;
    if (i < NNODE) { g_indeg[i] = 0; g_cursor[i] = 0; }
}

__global__ void k_hist(const int* __restrict__ dst) {
    int e = blockIdx.x * blockDim.x + threadIdx.x;
    if (e < NEDGE) atomicAdd(&g_indeg[dst[e]], 1);
}

__global__ void k_scan_partial() {
    __shared__ int sh[256];
    int b = blockIdx.x, t = threadIdx.x;
    sh[t] = g_indeg[b * 256 + t];
    __syncthreads();
    for (int s = 128; s > 0; s >>= 1) {
        if (t < s) sh[t] += sh[t + s];
        __syncthreads();
    }
    if (t == 0) g_part[b] = sh[0];
}

__global__ void k_scan_block() {
    __shared__ int sh[256];
    int t = threadIdx.x;
    int v = g_part[t];
    sh[t] = v;
    __syncthreads();
    for (int off = 1; off < 256; off <<= 1) {
        int xv = (t >= off) ? sh[t - off] : 0;
        __syncthreads();
        sh[t] += xv;
        __syncthreads();
    }
    g_part[t] = sh[t] - v;   // exclusive
}

__global__ void k_scan_final() {
    __shared__ int sh[256];
    int b = blockIdx.x, t = threadIdx.x;
    int v = g_indeg[b * 256 + t];
    sh[t] = v;
    __syncthreads();
    for (int off = 1; off < 256; off <<= 1) {
        int xv = (t >= off) ? sh[t - off] : 0;
        __syncthreads();
        sh[t] += xv;
        __syncthreads();
    }
    int excl = sh[t] - v + g_part[b];
    g_rowptr[b * 256 + t] = excl;
    if (b == 255 && t == 255) g_rowptr[NNODE] = excl + v;
    g_dinv[b * 256 + t] = rsqrtf((float)(v + 1));   // +1 self loop
}

__global__ void k_fill(const int* __restrict__ src, const int* __restrict__ dst) {
    int e = blockIdx.x * blockDim.x + threadIdx.x;
    if (e < NEDGE) {
        int d = dst[e];
        int p = atomicAdd(&g_cursor[d], 1);
        g_csr[g_rowptr[d] + p] = src[e];
    }
}

// ---------------- tiny meta-adjacency prep ----------------------------------
__global__ void k_copyA(const float* __restrict__ adj) {
    int i = blockIdx.x * blockDim.x + threadIdx.x;
    if (i < 4096) g_A[0][i] = adj[i];
}

__global__ void k_mm64(const float* __restrict__ A, const float* __restrict__ B,
                       float* __restrict__ C) {
    int c = threadIdx.x;
    for (int r = threadIdx.y; r < 64; r += blockDim.y) {
        float s = 0.f;
#pragma unroll 16
        for (int k = 0; k < 64; k++) s += A[r * 64 + k] * B[k * 64 + c];
        C[r * 64 + c] = s;
    }
}

__global__ void k_bsum(const float* __restrict__ gb) {
    int i = blockIdx.x * blockDim.x + threadIdx.x;
    if (i < NLAYER * 128) {
        int l = i / 128, c = i % 128;
        float s = 0.f;
        for (int j = 0; j < 4; j++) s += gb[(l * 4 + j) * 128 + c];
        g_bsum[l][c] = s;
    }
}

// ---------------- generic 64x64-tile GEMM (mix + head2) ----------------------
// C[M x N] = A[M x K](lda) @ B[K x N](ldb); 4x4/thread, BK=16.
__global__ void __launch_bounds__(256) k_gemm(
    const float* __restrict__ A, int lda,
    const float* __restrict__ B, int ldb,
    const float* __restrict__ bias, float* __restrict__ C,
    int ldc, int relu, int K)
{
    __shared__ float As[16][64];
    __shared__ float Bs[16][68];
    int tid  = threadIdx.x;
    int row0 = blockIdx.y * 64;
    int n0   = blockIdx.x * 64;
    int lm = tid >> 2, lk = (tid & 3) * 4;
    int bk = tid >> 4, bn = (tid & 15) * 4;
    int tm = (tid >> 4) * 4, tn = (tid & 15) * 4;
    float acc[4][4] = {};
    for (int k0 = 0; k0 < K; k0 += 16) {
        float4 av = *(const float4*)(A + (size_t)(row0 + lm) * lda + k0 + lk);
        As[lk + 0][lm] = av.x; As[lk + 1][lm] = av.y;
        As[lk + 2][lm] = av.z; As[lk + 3][lm] = av.w;
        *(float4*)&Bs[bk][bn] = *(const float4*)(B + (size_t)(k0 + bk) * ldb + n0 + bn);
        __syncthreads();
#pragma unroll
        for (int k = 0; k < 16; k++) {
            float4 a = *(const float4*)&As[k][tm];
            float4 b = *(const float4*)&Bs[k][tn];
            acc[0][0] += a.x * b.x; acc[0][1] += a.x * b.y; acc[0][2] += a.x * b.z; acc[0][3] += a.x * b.w;
            acc[1][0] += a.y * b.x; acc[1][1] += a.y * b.y; acc[1][2] += a.y * b.z; acc[1][3] += a.y * b.w;
            acc[2][0] += a.z * b.x; acc[2][1] += a.z * b.y; acc[2][2] += a.z * b.z; acc[2][3] += a.z * b.w;
            acc[3][0] += a.w * b.x; acc[3][1] += a.w * b.y; acc[3][2] += a.w * b.z; acc[3][3] += a.w * b.w;
        }
        __syncthreads();
    }
#pragma unroll
    for (int i = 0; i < 4; i++) {
        float4 o = make_float4(acc[i][0], acc[i][1], acc[i][2], acc[i][3]);
        if (bias) {
            o.x += bias[n0 + tn + 0]; o.y += bias[n0 + tn + 1];
            o.z += bias[n0 + tn + 2]; o.w += bias[n0 + tn + 3];
        }
        if (relu) {
            o.x = fmaxf(o.x, 0.f); o.y = fmaxf(o.y, 0.f);
            o.z = fmaxf(o.z, 0.f); o.w = fmaxf(o.w, 0.f);
        }
        *(float4*)(C + (size_t)(row0 + tm + i) * ldc + n0 + tn) = o;
    }
}

// ---------------- node GEMM: 128x128 tile, BK=32, 8x8/thread -----------------
// C[M x 128] = [A0 | A1-chunks] [M x K] @ B[K x 128]
// mode 0: C[r,:] = g_dinv[r] * acc      (layer GEMM -> Z)
// mode 1: C[r,:] = relu(acc + bias)     (head1)
__global__ void __launch_bounds__(256, 2) k_ngemm(
    const float* __restrict__ A0, const float* __restrict__ A1,
    const float* __restrict__ B, const float* __restrict__ bias,
    float* __restrict__ C, int K, int mode)
{
    __shared__ float As[32][132];
    __shared__ float Bs[32][132];
    int tid  = threadIdx.x;
    int row0 = blockIdx.x * 128;
    int am = tid >> 1,  ak = (tid & 1) * 16;
    int bk = tid >> 3,  bn = (tid & 7) * 16;
    int ty = tid >> 4,  tx = tid & 15;
    int r0 = ty * 4,    c0 = tx * 4;
    float acc[8][8] = {};

    for (int k0 = 0; k0 < K; k0 += 32) {
        const float* Ab = (k0 < 128) ? A0
                        : (A1 + (size_t)((k0 >> 7) - 1) * ((size_t)NNODE * 128));
        int kk = k0 & 127;
        const float* ap = Ab + (size_t)(row0 + am) * 128 + kk + ak;
#pragma unroll
        for (int q = 0; q < 4; q++) {
            float4 v = *(const float4*)(ap + q * 4);
            As[ak + q * 4 + 0][am] = v.x;
            As[ak + q * 4 + 1][am] = v.y;
            As[ak + q * 4 + 2][am] = v.z;
            As[ak + q * 4 + 3][am] = v.w;
        }
        const float* bp = B + (size_t)(k0 + bk) * 128 + bn;
#pragma unroll
        for (int q = 0; q < 4; q++)
            *(float4*)&Bs[bk][bn + q * 4] = *(const float4*)(bp + q * 4);
        __syncthreads();
#pragma unroll
        for (int k = 0; k < 32; k++) {
            float a[8], b[8];
            *(float4*)(a)     = *(const float4*)&As[k][r0];
            *(float4*)(a + 4) = *(const float4*)&As[k][r0 + 64];
            *(float4*)(b)     = *(const float4*)&Bs[k][c0];
            *(float4*)(b + 4) = *(const float4*)&Bs[k][c0 + 64];
#pragma unroll
            for (int i = 0; i < 8; i++)
#pragma unroll
                for (int j = 0; j < 8; j++)
                    acc[i][j] += a[i] * b[j];
        }
        __syncthreads();
    }

#pragma unroll
    for (int i = 0; i < 8; i++) {
        int r = row0 + r0 + ((i < 4) ? i : (60 + i));
        float scale = (mode == 0) ? g_dinv[r] : 1.0f;
#pragma unroll
        for (int h = 0; h < 2; h++) {
            int c = c0 + h * 64;
            float4 o = make_float4(acc[i][h*4+0], acc[i][h*4+1],
                                   acc[i][h*4+2], acc[i][h*4+3]);
            if (mode == 0) {
                o.x *= scale; o.y *= scale; o.z *= scale; o.w *= scale;
            } else {
                o.x = fmaxf(o.x + bias[c + 0], 0.f);
                o.y = fmaxf(o.y + bias[c + 1], 0.f);
                o.z = fmaxf(o.z + bias[c + 2], 0.f);
                o.w = fmaxf(o.w + bias[c + 3], 0.f);
            }
            *(float4*)(C + (size_t)r * 128 + c) = o;
        }
    }
}

// ---------------- edge aggregation -------------------------------------------
__global__ void __launch_bounds__(256) k_agg(const float* __restrict__ Z,
                                             const float* __restrict__ bsum,
                                             float* __restrict__ out) {
    int v = (blockIdx.x * 256 + threadIdx.x) >> 5;
    int lane = threadIdx.x & 31;
    if (v >= NNODE) return;
    float4 acc = *((const float4*)(Z + (size_t)v * 128) + lane);  // self loop
    int p = g_rowptr[v], p1 = g_rowptr[v + 1];
    for (; p + 1 < p1; p += 2) {
        int u0 = g_csr[p], u1 = g_csr[p + 1];
        float4 z0 = *((const float4*)(Z + (size_t)u0 * 128) + lane);
        float4 z1 = *((const float4*)(Z + (size_t)u1 * 128) + lane);
        acc.x += z0.x + z1.x; acc.y += z0.y + z1.y;
        acc.z += z0.z + z1.z; acc.w += z0.w + z1.w;
    }
    if (p < p1) {
        int u = g_csr[p];
        float4 z = *((const float4*)(Z + (size_t)u * 128) + lane);
        acc.x += z.x; acc.y += z.y; acc.z += z.z; acc.w += z.w;
    }
    float dv = g_dinv[v];
    float4 b = *((const float4*)bsum + lane);
    float4 o;
    o.x = fmaxf(dv * acc.x + b.x, 0.f);
    o.y = fmaxf(dv * acc.y + b.y, 0.f);
    o.z = fmaxf(dv * acc.z + b.z, 0.f);
    o.w = fmaxf(dv * acc.w + b.w, 0.f);
    *((float4*)(out + (size_t)v * 128) + lane) = o;
}

// ---------------- host orchestration -----------------------------------------
extern "C" void kernel_launch(void* const* d_in, const int* in_sizes, int n_in,
                              void* d_out, int out_size) {
    const float* x    = (const float*)d_in[0];
    const int*   sub  = (const int*)d_in[1];
    const float* adj  = (const float*)d_in[2];
    const float* gcnW = (const float*)d_in[3];
    const float* gcnB = (const float*)d_in[4];
    const float* W1   = (const float*)d_in[5];
    const float* b1   = (const float*)d_in[6];
    const float* W2   = (const float*)d_in[7];
    const float* b2   = (const float*)d_in[8];
    float* out = (float*)d_out;

    void* p;
    float *pY, *pX, *pS, *pZ, *pA, *pB;
    cudaGetSymbolAddress(&p, g_Y);    pY = (float*)p;
    cudaGetSymbolAddress(&p, g_X);    pX = (float*)p;
    cudaGetSymbolAddress(&p, g_S);    pS = (float*)p;
    cudaGetSymbolAddress(&p, g_Z);    pZ = (float*)p;
    cudaGetSymbolAddress(&p, g_A);    pA = (float*)p;
    cudaGetSymbolAddress(&p, g_bsum); pB = (float*)p;

    // graph preprocessing
    k_init<<<256, 256>>>();
    k_hist<<<NEDGE / 256, 256>>>(sub + NEDGE);
    k_scan_partial<<<256, 256>>>();
    k_scan_block<<<1, 256>>>();
    k_scan_final<<<256, 256>>>();
    k_fill<<<NEDGE / 256, 256>>>(sub, sub + NEDGE);

    // meta adjacency powers + summed biases
    k_copyA<<<16, 256>>>(adj);
    k_mm64<<<1, dim3(64, 16)>>>(pA, pA, pA + 4096);            // A^2
    k_mm64<<<1, dim3(64, 16)>>>(pA + 4096, pA, pA + 2 * 4096); // A^3
    k_bsum<<<2, 256>>>(gcnB);

    const float* cur = x;
    float* bufs[2] = { pX, pS };
    for (int l = 0; l < NLAYER; l++) {
        // Y[192 x 131072] = [A;A^2;A^3] @ Xv[64 x 131072]
        k_gemm<<<dim3(2048, 3), 256>>>(pA, 64, cur, 131072,
                                       nullptr, pY, 131072, 0, 64);
        // Z = dinv * ([X|Y1|Y2|Y3] @ gcnW[l])   (K = 512)
        k_ngemm<<<NNODE / 128, 256>>>(cur, pY, gcnW + (size_t)l * 4 * 16384,
                                      nullptr, pZ, 512, 0);
        // out = relu(dinv*(Z_v + sum Z_u) + bsum)
        k_agg<<<NNODE / 8, 256>>>(pZ, pB + l * 128, bufs[l & 1]);
        cur = bufs[l & 1];
    }

    // MLP head
    k_ngemm<<<NNODE / 128, 256>>>(cur, nullptr, W1, b1, pS, 128, 1);
    k_gemm<<<dim3(1, NNODE / 64), 256>>>(pS, 128, W2, 64, b2, out, 64, 0, 128);
}

// round 7
// speedup vs baseline: 2.8211x; 1.4030x over previous
#include <cuda_runtime.h>
#include <cuda_bf16.h>
#include <cstdint>

#define NNODE 65536
#define NEDGE 1048576
#define NLAYER 3

// ---------------- scratch (static device globals) ---------------------------
__device__ float g_dinv[NNODE];
__device__ int   g_indeg[NNODE];
__device__ int   g_rowptr[NNODE + 1];
__device__ int   g_cursor[NNODE];
__device__ int   g_csr[NEDGE];
__device__ int   g_part[256];
__device__ float g_A[3][64 * 64];              // [A, A^2, A^3] stacked
__device__ float g_bsum[NLAYER][128];
__device__ float g_Y[(size_t)3 * NNODE * 128]; // mixed features
__device__ float g_X[(size_t)NNODE * 128];
__device__ float g_S[(size_t)NNODE * 128];
__device__ float g_Z[(size_t)NNODE * 128];
// bf16 split weights, transposed to [n][k]
__device__ __nv_bfloat16 g_WLhi[3][128 * 512], g_WLlo[3][128 * 512];
__device__ __nv_bfloat16 g_W1hi[128 * 128],    g_W1lo[128 * 128];
__device__ __nv_bfloat16 g_W2hi[64 * 128],     g_W2lo[64 * 128];

// ================= helpers ====================================================
__device__ __forceinline__ uint32_t smem_to_u32(const void* p) {
    uint32_t a;
    asm("{ .reg .u64 t; cvta.to.shared.u64 t, %1; cvt.u32.u64 %0, t; }" : "=r"(a) : "l"(p));
    return a;
}
#define SMEM_SWIZZLE_128B(o) ((o) ^ (((o) >> 3) & 0x70))

#define LDSM_X4(r0, r1, r2, r3, addr) \
    asm volatile("ldmatrix.sync.aligned.m8n8.x4.shared.b16 {%0,%1,%2,%3}, [%4];" \
                 : "=r"(r0), "=r"(r1), "=r"(r2), "=r"(r3) : "r"(addr))

__device__ __forceinline__ void mma16816(float* c, const uint32_t* a, const uint32_t* b) {
    asm volatile(
        "mma.sync.aligned.m16n8k16.row.col.f32.bf16.bf16.f32 "
        "{%0,%1,%2,%3}, {%4,%5,%6,%7}, {%8,%9}, {%0,%1,%2,%3};"
        : "+f"(c[0]), "+f"(c[1]), "+f"(c[2]), "+f"(c[3])
        : "r"(a[0]), "r"(a[1]), "r"(a[2]), "r"(a[3]), "r"(b[0]), "r"(b[1]));
}

// ---------------- graph preprocessing ---------------------------------------
__global__ void k_init() {
    int i = blockIdx.x * blockDim.x + threadIdx.x;
    if (i < NNODE) { g_indeg[i] = 0; g_cursor[i] = 0; }
}
__global__ void k_hist(const int* __restrict__ dst) {
    int e = blockIdx.x * blockDim.x + threadIdx.x;
    if (e < NEDGE) atomicAdd(&g_indeg[dst[e]], 1);
}
__global__ void k_scan_partial() {
    __shared__ int sh[256];
    int b = blockIdx.x, t = threadIdx.x;
    sh[t] = g_indeg[b * 256 + t];
    __syncthreads();
    for (int s = 128; s > 0; s >>= 1) {
        if (t < s) sh[t] += sh[t + s];
        __syncthreads();
    }
    if (t == 0) g_part[b] = sh[0];
}
__global__ void k_scan_block() {
    __shared__ int sh[256];
    int t = threadIdx.x;
    int v = g_part[t];
    sh[t] = v;
    __syncthreads();
    for (int off = 1; off < 256; off <<= 1) {
        int xv = (t >= off) ? sh[t - off] : 0;
        __syncthreads();
        sh[t] += xv;
        __syncthreads();
    }
    g_part[t] = sh[t] - v;
}
__global__ void k_scan_final() {
    __shared__ int sh[256];
    int b = blockIdx.x, t = threadIdx.x;
    int v = g_indeg[b * 256 + t];
    sh[t] = v;
    __syncthreads();
    for (int off = 1; off < 256; off <<= 1) {
        int xv = (t >= off) ? sh[t - off] : 0;
        __syncthreads();
        sh[t] += xv;
        __syncthreads();
    }
    int excl = sh[t] - v + g_part[b];
    g_rowptr[b * 256 + t] = excl;
    if (b == 255 && t == 255) g_rowptr[NNODE] = excl + v;
    g_dinv[b * 256 + t] = rsqrtf((float)(v + 1));
}
__global__ void k_fill(const int* __restrict__ src, const int* __restrict__ dst) {
    int e = blockIdx.x * blockDim.x + threadIdx.x;
    if (e < NEDGE) {
        int d = dst[e];
        int p = atomicAdd(&g_cursor[d], 1);
        g_csr[g_rowptr[d] + p] = src[e];
    }
}

// ---------------- tiny meta prep ---------------------------------------------
__global__ void k_copyA(const float* __restrict__ adj) {
    int i = blockIdx.x * blockDim.x + threadIdx.x;
    if (i < 4096) g_A[0][i] = adj[i];
}
__global__ void k_mm64(const float* __restrict__ A, const float* __restrict__ B,
                       float* __restrict__ C) {
    int c = threadIdx.x;
    for (int r = threadIdx.y; r < 64; r += blockDim.y) {
        float s = 0.f;
#pragma unroll 16
        for (int k = 0; k < 64; k++) s += A[r * 64 + k] * B[k * 64 + c];
        C[r * 64 + c] = s;
    }
}
__global__ void k_bsum(const float* __restrict__ gb) {
    int i = blockIdx.x * blockDim.x + threadIdx.x;
    if (i < NLAYER * 128) {
        int l = i / 128, c = i % 128;
        float s = 0.f;
        for (int j = 0; j < 4; j++) s += gb[(l * 4 + j) * 128 + c];
        g_bsum[l][c] = s;
    }
}

// weight prep: W[K x N] -> Wt_hi/lo[n][k] bf16 split
__global__ void k_wprep(const float* __restrict__ W, __nv_bfloat16* __restrict__ hi,
                        __nv_bfloat16* __restrict__ lo, int K, int N) {
    int idx = blockIdx.x * 256 + threadIdx.x;
    if (idx >= K * N) return;
    int n = idx / K, k = idx % K;
    float v = W[(size_t)k * N + n];
    __nv_bfloat16 h = __float2bfloat16(v);
    hi[idx] = h;
    lo[idx] = __float2bfloat16(v - __bfloat162float(h));
}

// ---------------- mix GEMM (R2-proven fp32): Y = Acat(192x64) @ Xv ------------
__global__ void __launch_bounds__(256) k_gemm(
    const float* __restrict__ A, int lda,
    const float* __restrict__ B, int ldb,
    float* __restrict__ C, int ldc, int K)
{
    __shared__ float As[16][64];
    __shared__ float Bs[16][68];
    int tid  = threadIdx.x;
    int row0 = blockIdx.y * 64;
    int n0   = blockIdx.x * 64;
    int lm = tid >> 2, lk = (tid & 3) * 4;
    int bk = tid >> 4, bn = (tid & 15) * 4;
    int tm = (tid >> 4) * 4, tn = (tid & 15) * 4;
    float acc[4][4] = {};
    for (int k0 = 0; k0 < K; k0 += 16) {
        float4 av = *(const float4*)(A + (size_t)(row0 + lm) * lda + k0 + lk);
        As[lk + 0][lm] = av.x; As[lk + 1][lm] = av.y;
        As[lk + 2][lm] = av.z; As[lk + 3][lm] = av.w;
        *(float4*)&Bs[bk][bn] = *(const float4*)(B + (size_t)(k0 + bk) * ldb + n0 + bn);
        __syncthreads();
#pragma unroll
        for (int k = 0; k < 16; k++) {
            float4 a = *(const float4*)&As[k][tm];
            float4 b = *(const float4*)&Bs[k][tn];
            acc[0][0] += a.x * b.x; acc[0][1] += a.x * b.y; acc[0][2] += a.x * b.z; acc[0][3] += a.x * b.w;
            acc[1][0] += a.y * b.x; acc[1][1] += a.y * b.y; acc[1][2] += a.y * b.z; acc[1][3] += a.y * b.w;
            acc[2][0] += a.z * b.x; acc[2][1] += a.z * b.y; acc[2][2] += a.z * b.z; acc[2][3] += a.z * b.w;
            acc[3][0] += a.w * b.x; acc[3][1] += a.w * b.y; acc[3][2] += a.w * b.z; acc[3][3] += a.w * b.w;
        }
        __syncthreads();
    }
#pragma unroll
    for (int i = 0; i < 4; i++) {
        float4 o = make_float4(acc[i][0], acc[i][1], acc[i][2], acc[i][3]);
        *(float4*)(C + (size_t)(row0 + tm + i) * ldc + n0 + tn) = o;
    }
}

// ---------------- mma.sync node GEMM (STATIC smem, 64x64 tile) ----------------
// C[65536 x NOUT] = Acat[65536 x (nChunks*64)] @ Wt^T (bf16 2-term split, 3 products)
// grid = (1024, NOUT/64). MODE 0: raw H (no scaling!); MODE 1: relu(+bias); MODE 2: +bias.
template <int NOUT, int MODE>
__global__ void __launch_bounds__(256) k_mma(
    const float* __restrict__ A0, const float* __restrict__ A1,
    const __nv_bfloat16* __restrict__ wtHi, const __nv_bfloat16* __restrict__ wtLo,
    const float* __restrict__ bias, float* __restrict__ C, int nChunks)
{
    __shared__ __align__(1024) unsigned char sAh[8192];   // 64 rows x 64 bf16
    __shared__ __align__(1024) unsigned char sAl[8192];
    __shared__ __align__(1024) unsigned char sBh[8192];   // 64 rows x 64 bf16
    __shared__ __align__(1024) unsigned char sBl[8192];
    const uint32_t aHiA = smem_to_u32(sAh), aLoA = smem_to_u32(sAl);
    const uint32_t bHiA = smem_to_u32(sBh), bLoA = smem_to_u32(sBl);
    int tid = threadIdx.x, lane = tid & 31, wid = tid >> 5;
    int wm = wid & 3, wn = wid >> 2;          // 4x2 warp grid over 64x64 tile
    int row0 = blockIdx.x * 64;
    int n0   = blockIdx.y * 64;
    int Ktot = nChunks * 64;
    int g = lane >> 2, t4 = lane & 3;
    // ldmatrix lane addressing
    int aRow = lane & 15;
    int aKb  = (lane >> 4) * 16;
    int bRow = ((lane >> 4) << 3) + (lane & 7);
    int bKb  = ((lane >> 3) & 1) * 16;

    float acc[4][4] = {};                      // 4 n8-tiles x 4

    for (int c = 0; c < nChunks; c++) {
        const float* S;
        int kk;                                // local K offset within source buffer
        if (c < 2) { S = A0; kk = c * 64; }
        else { S = A1 + (size_t)((c - 2) >> 1) * ((size_t)NNODE * 128); kk = (c & 1) * 64; }
        const int kb = c * 64;                 // global K offset for weights
        const float* ap = S + (size_t)row0 * 128 + kk;
        // A tile: 64 rows x 64 fp32 -> hi/lo bf16, swizzled
#pragma unroll
        for (int q = 0; q < 4; q++) {
            int idx = tid + 256 * q;           // 0..1023
            int row = idx >> 4, k4 = (idx & 15) * 4;
            float4 v = *(const float4*)(ap + (size_t)row * 128 + k4);
            __nv_bfloat16 h0 = __float2bfloat16(v.x), h1 = __float2bfloat16(v.y);
            __nv_bfloat16 h2 = __float2bfloat16(v.z), h3 = __float2bfloat16(v.w);
            __nv_bfloat16 l0 = __float2bfloat16(v.x - __bfloat162float(h0));
            __nv_bfloat16 l1 = __float2bfloat16(v.y - __bfloat162float(h1));
            __nv_bfloat16 l2 = __float2bfloat16(v.z - __bfloat162float(h2));
            __nv_bfloat16 l3 = __float2bfloat16(v.w - __bfloat162float(h3));
            uint2 hp, lp;
            hp.x = (uint32_t)*(unsigned short*)&h0 | ((uint32_t)*(unsigned short*)&h1 << 16);
            hp.y = (uint32_t)*(unsigned short*)&h2 | ((uint32_t)*(unsigned short*)&h3 << 16);
            lp.x = (uint32_t)*(unsigned short*)&l0 | ((uint32_t)*(unsigned short*)&l1 << 16);
            lp.y = (uint32_t)*(unsigned short*)&l2 | ((uint32_t)*(unsigned short*)&l3 << 16);
            uint32_t sw = SMEM_SWIZZLE_128B((uint32_t)(row * 128 + k4 * 2));
            *(uint2*)(sAh + sw) = hp;
            *(uint2*)(sAl + sw) = lp;
        }
        // B tile: 64 rows (global n0+row) x 64 bf16 hi/lo (pre-split), swizzled
#pragma unroll
        for (int q = 0; q < 4; q++) {
            int idx = tid + 256 * q;
            int row = idx >> 4, k4 = (idx & 15) * 4;
            uint2 h = *(const uint2*)(wtHi + (size_t)(n0 + row) * Ktot + kb + k4);
            uint2 l = *(const uint2*)(wtLo + (size_t)(n0 + row) * Ktot + kb + k4);
            uint32_t sw = SMEM_SWIZZLE_128B((uint32_t)(row * 128 + k4 * 2));
            *(uint2*)(sBh + sw) = h;
            *(uint2*)(sBl + sw) = l;
        }
        __syncthreads();
#pragma unroll
        for (int ks = 0; ks < 4; ks++) {
            uint32_t ah[4], al[4];
            uint32_t aOff = SMEM_SWIZZLE_128B(
                (uint32_t)((wm * 16 + aRow) * 128 + ks * 32 + aKb));
            LDSM_X4(ah[0], ah[1], ah[2], ah[3], aHiA + aOff);
            LDSM_X4(al[0], al[1], al[2], al[3], aLoA + aOff);
            uint32_t bh[4][2], bl[4][2];
#pragma unroll
            for (int np = 0; np < 2; np++) {
                int nb = wn * 32 + np * 16;
                uint32_t bOff = SMEM_SWIZZLE_128B(
                    (uint32_t)((nb + bRow) * 128 + ks * 32 + bKb));
                LDSM_X4(bh[2 * np][0], bh[2 * np][1], bh[2 * np + 1][0], bh[2 * np + 1][1],
                        bHiA + bOff);
                LDSM_X4(bl[2 * np][0], bl[2 * np][1], bl[2 * np + 1][0], bl[2 * np + 1][1],
                        bLoA + bOff);
            }
#pragma unroll
            for (int nt = 0; nt < 4; nt++) {
                mma16816(acc[nt], ah, bh[nt]);
                mma16816(acc[nt], al, bh[nt]);
                mma16816(acc[nt], ah, bl[nt]);
            }
        }
        __syncthreads();
    }

    // epilogue (no dinv here — folded into k_agg so k_mma has no prep dependency)
#pragma unroll
    for (int half = 0; half < 2; half++) {
        int r = row0 + wm * 16 + g + half * 8;
        float* Cr = C + (size_t)r * NOUT;
#pragma unroll
        for (int nt = 0; nt < 4; nt++) {
            int col = n0 + wn * 32 + nt * 8 + t4 * 2;
            float v0 = acc[nt][half * 2 + 0];
            float v1 = acc[nt][half * 2 + 1];
            if (MODE >= 1) {
                v0 += bias[col]; v1 += bias[col + 1];
                if (MODE == 1) { v0 = fmaxf(v0, 0.f); v1 = fmaxf(v1, 0.f); }
            }
            *(float2*)(Cr + col) = make_float2(v0, v1);
        }
    }
}

// ---------------- edge aggregation (normalization folded in) ------------------
// out[v] = relu(dinv[v]*(dinv[v]*H[v] + sum_u dinv[u]*H[u]) + bsum)
__global__ void __launch_bounds__(256) k_agg(const float* __restrict__ H,
                                             const float* __restrict__ bsum,
                                             float* __restrict__ out) {
    int v = (blockIdx.x * 256 + threadIdx.x) >> 5;
    int lane = threadIdx.x & 31;
    if (v >= NNODE) return;
    float dv = g_dinv[v];
    float4 zv = *((const float4*)(H + (size_t)v * 128) + lane);
    float4 acc = make_float4(dv * zv.x, dv * zv.y, dv * zv.z, dv * zv.w);  // self loop
    int p = g_rowptr[v], p1 = g_rowptr[v + 1];
    for (; p < p1; p++) {
        int u = g_csr[p];
        float du = g_dinv[u];
        float4 z = *((const float4*)(H + (size_t)u * 128) + lane);
        acc.x += du * z.x; acc.y += du * z.y;
        acc.z += du * z.z; acc.w += du * z.w;
    }
    float4 b = *((const float4*)bsum + lane);
    float4 o;
    o.x = fmaxf(dv * acc.x + b.x, 0.f);
    o.y = fmaxf(dv * acc.y + b.y, 0.f);
    o.z = fmaxf(dv * acc.z + b.z, 0.f);
    o.w = fmaxf(dv * acc.w + b.w, 0.f);
    *((float4*)(out + (size_t)v * 128) + lane) = o;
}

// ---------------- host orchestration -----------------------------------------
extern "C" void kernel_launch(void* const* d_in, const int* in_sizes, int n_in,
                              void* d_out, int out_size) {
    const float* x    = (const float*)d_in[0];
    const int*   sub  = (const int*)d_in[1];
    const float* adj  = (const float*)d_in[2];
    const float* gcnW = (const float*)d_in[3];
    const float* gcnB = (const float*)d_in[4];
    const float* W1   = (const float*)d_in[5];
    const float* b1   = (const float*)d_in[6];
    const float* W2   = (const float*)d_in[7];
    const float* b2   = (const float*)d_in[8];
    float* out = (float*)d_out;

    void* p;
    float *pY, *pX, *pS, *pZ, *pA, *pB;
    __nv_bfloat16 *pWLh, *pWLl, *pW1h, *pW1l, *pW2h, *pW2l;
    cudaGetSymbolAddress(&p, g_Y);    pY = (float*)p;
    cudaGetSymbolAddress(&p, g_X);    pX = (float*)p;
    cudaGetSymbolAddress(&p, g_S);    pS = (float*)p;
    cudaGetSymbolAddress(&p, g_Z);    pZ = (float*)p;
    cudaGetSymbolAddress(&p, g_A);    pA = (float*)p;
    cudaGetSymbolAddress(&p, g_bsum); pB = (float*)p;
    cudaGetSymbolAddress(&p, g_WLhi); pWLh = (__nv_bfloat16*)p;
    cudaGetSymbolAddress(&p, g_WLlo); pWLl = (__nv_bfloat16*)p;
    cudaGetSymbolAddress(&p, g_W1hi); pW1h = (__nv_bfloat16*)p;
    cudaGetSymbolAddress(&p, g_W1lo); pW1l = (__nv_bfloat16*)p;
    cudaGetSymbolAddress(&p, g_W2hi); pW2h = (__nv_bfloat16*)p;
    cudaGetSymbolAddress(&p, g_W2lo); pW2l = (__nv_bfloat16*)p;

    // launches 0-4: exactly the deps of the first k_mma
    k_copyA<<<16, 256>>>(adj);                                  // 0
    k_mm64<<<1, dim3(64, 16)>>>(pA, pA, pA + 4096);             // 1: A^2
    k_mm64<<<1, dim3(64, 16)>>>(pA + 4096, pA, pA + 2 * 4096);  // 2: A^3
    k_wprep<<<(512 * 128 + 255) / 256, 256>>>(gcnW, pWLh, pWLl, 512, 128);  // 3
    k_gemm<<<dim3(2048, 3), 256>>>(pA, 64, x, 131072, pY, 131072, 64);      // 4: mix L0
    // launch 5: node GEMM layer 0  (<- ncu capture slot; no dinv dependency)
    k_mma<128, 0><<<dim3(1024, 2), 256>>>(x, pY, pWLh, pWLl, nullptr, pZ, 8);

    // graph preprocessing (needed before first k_agg)
    k_init<<<256, 256>>>();
    k_hist<<<NEDGE / 256, 256>>>(sub + NEDGE);
    k_scan_partial<<<256, 256>>>();
    k_scan_block<<<1, 256>>>();
    k_scan_final<<<256, 256>>>();
    k_fill<<<NEDGE / 256, 256>>>(sub, sub + NEDGE);
    // remaining weight prep
    k_wprep<<<(512 * 128 + 255) / 256, 256>>>(gcnW + 65536, pWLh + 65536, pWLl + 65536, 512, 128);
    k_wprep<<<(512 * 128 + 255) / 256, 256>>>(gcnW + 131072, pWLh + 131072, pWLl + 131072, 512, 128);
    k_wprep<<<(128 * 128 + 255) / 256, 256>>>(W1, pW1h, pW1l, 128, 128);
    k_wprep<<<(128 * 64 + 255) / 256, 256>>>(W2, pW2h, pW2l, 128, 64);
    k_bsum<<<2, 256>>>(gcnB);

    // layer 0 aggregation
    float* bufs[2] = { pX, pS };
    k_agg<<<NNODE / 8, 256>>>(pZ, pB, bufs[0]);
    const float* cur = bufs[0];
    // layers 1..2
    for (int l = 1; l < NLAYER; l++) {
        k_gemm<<<dim3(2048, 3), 256>>>(pA, 64, cur, 131072, pY, 131072, 64);
        k_mma<128, 0><<<dim3(1024, 2), 256>>>(cur, pY, pWLh + (size_t)l * 65536,
                                              pWLl + (size_t)l * 65536, nullptr, pZ, 8);
        k_agg<<<NNODE / 8, 256>>>(pZ, pB + l * 128, bufs[l & 1]);
        cur = bufs[l & 1];
    }
    // MLP head
    k_mma<128, 1><<<dim3(1024, 2), 256>>>(cur, nullptr, pW1h, pW1l, b1, pZ, 2);
    k_mma<64, 2><<<dim3(1024, 1), 256>>>(pZ, nullptr, pW2h, pW2l, b2, out, 2);
}

// round 10
// speedup vs baseline: 2.8975x; 1.0271x over previous
#include <cuda_runtime.h>
#include <cuda_bf16.h>
#include <cstdint>

#define NNODE 65536
#define NEDGE 1048576
#define NLAYER 3

// ---------------- scratch (static device globals) ---------------------------
__device__ float g_dinv[NNODE];
__device__ int   g_indeg[NNODE];
__device__ int   g_rowptr[NNODE + 1];
__device__ int   g_cursor[NNODE];
__device__ int   g_csr[NEDGE];
__device__ int   g_part[256];
__device__ float g_A[3][64 * 64];              // [A, A^2, A^3] stacked
__device__ __nv_bfloat16 g_Ahi[3 * 4096], g_Alo[3 * 4096];
__device__ float g_bsum[NLAYER][128];
__device__ float g_Y[(size_t)3 * NNODE * 128]; // mixed features
__device__ float g_X[(size_t)NNODE * 128];
__device__ float g_S[(size_t)NNODE * 128];
__device__ float g_Z[(size_t)NNODE * 128];
// bf16 split weights, transposed to [n][k]
__device__ __nv_bfloat16 g_WLhi[3][128 * 512], g_WLlo[3][128 * 512];
__device__ __nv_bfloat16 g_W1hi[128 * 128],    g_W1lo[128 * 128];
__device__ __nv_bfloat16 g_W2hi[64 * 128],     g_W2lo[64 * 128];

// ================= helpers ====================================================
__device__ __forceinline__ uint32_t smem_to_u32(const void* p) {
    uint32_t a;
    asm("{ .reg .u64 t; cvta.to.shared.u64 t, %1; cvt.u32.u64 %0, t; }" : "=r"(a) : "l"(p));
    return a;
}
#define SMEM_SWIZZLE_128B(o) ((o) ^ (((o) >> 3) & 0x70))

#define LDSM_X4(r0, r1, r2, r3, addr) \
    asm volatile("ldmatrix.sync.aligned.m8n8.x4.shared.b16 {%0,%1,%2,%3}, [%4];" \
                 : "=r"(r0), "=r"(r1), "=r"(r2), "=r"(r3) : "r"(addr))

__device__ __forceinline__ void mma16816(float* c, const uint32_t* a, const uint32_t* b) {
    asm volatile(
        "mma.sync.aligned.m16n8k16.row.col.f32.bf16.bf16.f32 "
        "{%0,%1,%2,%3}, {%4,%5,%6,%7}, {%8,%9}, {%0,%1,%2,%3};"
        : "+f"(c[0]), "+f"(c[1]), "+f"(c[2]), "+f"(c[3])
        : "r"(a[0]), "r"(a[1]), "r"(a[2]), "r"(a[3]), "r"(b[0]), "r"(b[1]));
}

__device__ __forceinline__ void bf16split4(float4 v, uint2& hp, uint2& lp) {
    __nv_bfloat16 h0 = __float2bfloat16(v.x), h1 = __float2bfloat16(v.y);
    __nv_bfloat16 h2 = __float2bfloat16(v.z), h3 = __float2bfloat16(v.w);
    __nv_bfloat16 l0 = __float2bfloat16(v.x - __bfloat162float(h0));
    __nv_bfloat16 l1 = __float2bfloat16(v.y - __bfloat162float(h1));
    __nv_bfloat16 l2 = __float2bfloat16(v.z - __bfloat162float(h2));
    __nv_bfloat16 l3 = __float2bfloat16(v.w - __bfloat162float(h3));
    hp.x = (uint32_t)*(unsigned short*)&h0 | ((uint32_t)*(unsigned short*)&h1 << 16);
    hp.y = (uint32_t)*(unsigned short*)&h2 | ((uint32_t)*(unsigned short*)&h3 << 16);
    lp.x = (uint32_t)*(unsigned short*)&l0 | ((uint32_t)*(unsigned short*)&l1 << 16);
    lp.y = (uint32_t)*(unsigned short*)&l2 | ((uint32_t)*(unsigned short*)&l3 << 16);
}

// ---------------- graph preprocessing ---------------------------------------
__global__ void k_init() {
    int i = blockIdx.x * blockDim.x + threadIdx.x;
    if (i < NNODE) { g_indeg[i] = 0; g_cursor[i] = 0; }
}
__global__ void k_hist(const int* __restrict__ dst) {
    int e = blockIdx.x * blockDim.x + threadIdx.x;
    if (e < NEDGE) atomicAdd(&g_indeg[dst[e]], 1);
}
__global__ void k_scan_partial() {
    __shared__ int sh[256];
    int b = blockIdx.x, t = threadIdx.x;
    sh[t] = g_indeg[b * 256 + t];
    __syncthreads();
    for (int s = 128; s > 0; s >>= 1) {
        if (t < s) sh[t] += sh[t + s];
        __syncthreads();
    }
    if (t == 0) g_part[b] = sh[0];
}
__global__ void k_scan_block() {
    __shared__ int sh[256];
    int t = threadIdx.x;
    int v = g_part[t];
    sh[t] = v;
    __syncthreads();
    for (int off = 1; off < 256; off <<= 1) {
        int xv = (t >= off) ? sh[t - off] : 0;
        __syncthreads();
        sh[t] += xv;
        __syncthreads();
    }
    g_part[t] = sh[t] - v;
}
__global__ void k_scan_final() {
    __shared__ int sh[256];
    int b = blockIdx.x, t = threadIdx.x;
    int v = g_indeg[b * 256 + t];
    sh[t] = v;
    __syncthreads();
    for (int off = 1; off < 256; off <<= 1) {
        int xv = (t >= off) ? sh[t - off] : 0;
        __syncthreads();
        sh[t] += xv;
        __syncthreads();
    }
    int excl = sh[t] - v + g_part[b];
    g_rowptr[b * 256 + t] = excl;
    if (b == 255 && t == 255) g_rowptr[NNODE] = excl + v;
    g_dinv[b * 256 + t] = rsqrtf((float)(v + 1));
}
__global__ void k_fill(const int* __restrict__ src, const int* __restrict__ dst) {
    int e = blockIdx.x * blockDim.x + threadIdx.x;
    if (e < NEDGE) {
        int d = dst[e];
        int p = atomicAdd(&g_cursor[d], 1);
        g_csr[g_rowptr[d] + p] = src[e];
    }
}

// ---------------- tiny meta prep ---------------------------------------------
__global__ void k_copyA(const float* __restrict__ adj) {
    int i = blockIdx.x * blockDim.x + threadIdx.x;
    if (i < 4096) g_A[0][i] = adj[i];
}
__global__ void k_mm64(const float* __restrict__ A, const float* __restrict__ B,
                       float* __restrict__ C) {
    int c = threadIdx.x;
    for (int r = threadIdx.y; r < 64; r += blockDim.y) {
        float s = 0.f;
#pragma unroll 16
        for (int k = 0; k < 64; k++) s += A[r * 64 + k] * B[k * 64 + c];
        C[r * 64 + c] = s;
    }
}
__global__ void k_aprep() {
    int i = blockIdx.x * blockDim.x + threadIdx.x;
    if (i < 3 * 4096) {
        float v = g_A[0][i];
        __nv_bfloat16 h = __float2bfloat16(v);
        g_Ahi[i] = h;
        g_Alo[i] = __float2bfloat16(v - __bfloat162float(h));
    }
}
__global__ void k_bsum(const float* __restrict__ gb) {
    int i = blockIdx.x * blockDim.x + threadIdx.x;
    if (i < NLAYER * 128) {
        int l = i / 128, c = i % 128;
        float s = 0.f;
        for (int j = 0; j < 4; j++) s += gb[(l * 4 + j) * 128 + c];
        g_bsum[l][c] = s;
    }
}

// weight prep: W[K x N] -> Wt_hi/lo[n][k] bf16 split
__global__ void k_wprep(const float* __restrict__ W, __nv_bfloat16* __restrict__ hi,
                        __nv_bfloat16* __restrict__ lo, int K, int N) {
    int idx = blockIdx.x * 256 + threadIdx.x;
    if (idx >= K * N) return;
    int n = idx / K, k = idx % K;
    float v = W[(size_t)k * N + n];
    __nv_bfloat16 h = __float2bfloat16(v);
    hi[idx] = h;
    lo[idx] = __float2bfloat16(v - __bfloat162float(h));
}

// ---------------- HMMA mix: Y_i[64 x 131072] = A_i[64x64] @ X[64x131072] ------
// grid (2048, 3), block 256. X tile stored TRANSPOSED into smem ([col][j]) so the
// B operand uses the plain-ldmatrix path proven in k_mma (no .trans anywhere).
__global__ void __launch_bounds__(256) k_mixmma(const float* __restrict__ X,
                                                float* __restrict__ Y) {
    __shared__ __align__(1024) unsigned char sAh[8192];   // 64 n-rows x 64 bf16
    __shared__ __align__(1024) unsigned char sAl[8192];
    __shared__ __align__(1024) unsigned char sXh[8192];   // 64 col-rows x 64(j) bf16
    __shared__ __align__(1024) unsigned char sXl[8192];
    const uint32_t aHiA = smem_to_u32(sAh), aLoA = smem_to_u32(sAl);
    const uint32_t xHiA = smem_to_u32(sXh), xLoA = smem_to_u32(sXl);
    int tid = threadIdx.x, lane = tid & 31, wid = tid >> 5;
    int wm = wid & 3, wn = wid >> 2;
    int i = blockIdx.y;
    int col0 = blockIdx.x * 64;
    int g = lane >> 2, t4 = lane & 3;
    int aRow = lane & 15, aKb = (lane >> 4) * 16;
    int bRow = ((lane >> 4) << 3) + (lane & 7);
    int bKb  = ((lane >> 3) & 1) * 16;

    // load A_i (pre-split bf16) into swizzled smem: [n][j], 128B rows.
    // FULL tile = 64 rows x 16 uint2/row = 1024 units (R8/R9 bug: only 512 loaded)
#pragma unroll
    for (int q = 0; q < 4; q++) {
        int idx = tid + 256 * q;               // 0..1023 uint2 units (4 bf16 each)
        int row = idx >> 4, k4 = (idx & 15) * 4;
        uint2 h = *(const uint2*)(g_Ahi + i * 4096 + row * 64 + k4);
        uint2 l = *(const uint2*)(g_Alo + i * 4096 + row * 64 + k4);
        uint32_t sw = SMEM_SWIZZLE_128B((uint32_t)(row * 128 + k4 * 2));
        *(uint2*)(sAh + sw) = h;
        *(uint2*)(sAl + sw) = l;
    }
    // load X tile 64(j) x 64(col) fp32 and store TRANSPOSED: smem[col][j]
#pragma unroll
    for (int q = 0; q < 4; q++) {
        int idx = tid + 256 * q;
        int j = idx >> 4, c4 = (idx & 15) * 4;
        float4 v = *(const float4*)(X + (size_t)j * 131072 + col0 + c4);
        float f[4] = { v.x, v.y, v.z, v.w };
#pragma unroll
        for (int e = 0; e < 4; e++) {
            __nv_bfloat16 h = __float2bfloat16(f[e]);
            __nv_bfloat16 l = __float2bfloat16(f[e] - __bfloat162float(h));
            uint32_t sw = SMEM_SWIZZLE_128B((uint32_t)((c4 + e) * 128 + j * 2));
            *(__nv_bfloat16*)(sXh + sw) = h;
            *(__nv_bfloat16*)(sXl + sw) = l;
        }
    }
    __syncthreads();

    float acc[4][4] = {};
#pragma unroll
    for (int ks = 0; ks < 4; ks++) {
        uint32_t ah[4], al[4];
        uint32_t aOff = SMEM_SWIZZLE_128B(
            (uint32_t)((wm * 16 + aRow) * 128 + ks * 32 + aKb));
        LDSM_X4(ah[0], ah[1], ah[2], ah[3], aHiA + aOff);
        LDSM_X4(al[0], al[1], al[2], al[3], aLoA + aOff);
        uint32_t bh[4][2], bl[4][2];
#pragma unroll
        for (int np = 0; np < 2; np++) {
            int nb = wn * 32 + np * 16;
            uint32_t bOff = SMEM_SWIZZLE_128B(
                (uint32_t)((nb + bRow) * 128 + ks * 32 + bKb));
            LDSM_X4(bh[2 * np][0], bh[2 * np][1], bh[2 * np + 1][0], bh[2 * np + 1][1],
                    xHiA + bOff);
            LDSM_X4(bl[2 * np][0], bl[2 * np][1], bl[2 * np + 1][0], bl[2 * np + 1][1],
                    xLoA + bOff);
        }
#pragma unroll
        for (int nt = 0; nt < 4; nt++) {
            mma16816(acc[nt], ah, bh[nt]);
            mma16816(acc[nt], al, bh[nt]);
            mma16816(acc[nt], ah, bl[nt]);
        }
    }

    float* Yi = Y + (size_t)i * NNODE * 128;
#pragma unroll
    for (int half = 0; half < 2; half++) {
        int r = wm * 16 + g + half * 8;        // meta-node row n
        float* Yr = Yi + (size_t)r * 131072;
#pragma unroll
        for (int nt = 0; nt < 4; nt++) {
            int col = col0 + wn * 32 + nt * 8 + t4 * 2;
            *(float2*)(Yr + col) = make_float2(acc[nt][half * 2 + 0],
                                               acc[nt][half * 2 + 1]);
        }
    }
}

// ---------------- mma.sync node GEMM (STATIC smem, 64x64 tile) ----------------
// C[65536 x NOUT] = Acat[65536 x (nChunks*64)] @ Wt^T (bf16 2-term split, 3 products)
// grid = (1024, NOUT/64). MODE 0: raw H; MODE 1: relu(+bias); MODE 2: +bias.
template <int NOUT, int MODE>
__global__ void __launch_bounds__(256) k_mma(
    const float* __restrict__ A0, const float* __restrict__ A1,
    const __nv_bfloat16* __restrict__ wtHi, const __nv_bfloat16* __restrict__ wtLo,
    const float* __restrict__ bias, float* __restrict__ C, int nChunks)
{
    __shared__ __align__(1024) unsigned char sAh[8192];
    __shared__ __align__(1024) unsigned char sAl[8192];
    __shared__ __align__(1024) unsigned char sBh[8192];
    __shared__ __align__(1024) unsigned char sBl[8192];
    const uint32_t aHiA = smem_to_u32(sAh), aLoA = smem_to_u32(sAl);
    const uint32_t bHiA = smem_to_u32(sBh), bLoA = smem_to_u32(sBl);
    int tid = threadIdx.x, lane = tid & 31, wid = tid >> 5;
    int wm = wid & 3, wn = wid >> 2;
    int row0 = blockIdx.x * 64;
    int n0   = blockIdx.y * 64;
    int Ktot = nChunks * 64;
    int g = lane >> 2, t4 = lane & 3;
    int aRow = lane & 15;
    int aKb  = (lane >> 4) * 16;
    int bRow = ((lane >> 4) << 3) + (lane & 7);
    int bKb  = ((lane >> 3) & 1) * 16;

    float acc[4][4] = {};

    for (int c = 0; c < nChunks; c++) {
        const float* S;
        int kk;
        if (c < 2) { S = A0; kk = c * 64; }
        else { S = A1 + (size_t)((c - 2) >> 1) * ((size_t)NNODE * 128); kk = (c & 1) * 64; }
        const int kb = c * 64;
        const float* ap = S + (size_t)row0 * 128 + kk;
#pragma unroll
        for (int q = 0; q < 4; q++) {
            int idx = tid + 256 * q;
            int row = idx >> 4, k4 = (idx & 15) * 4;
            float4 v = *(const float4*)(ap + (size_t)row * 128 + k4);
            uint2 hp, lp;
            bf16split4(v, hp, lp);
            uint32_t sw = SMEM_SWIZZLE_128B((uint32_t)(row * 128 + k4 * 2));
            *(uint2*)(sAh + sw) = hp;
            *(uint2*)(sAl + sw) = lp;
        }
#pragma unroll
        for (int q = 0; q < 4; q++) {
            int idx = tid + 256 * q;
            int row = idx >> 4, k4 = (idx & 15) * 4;
            uint2 h = *(const uint2*)(wtHi + (size_t)(n0 + row) * Ktot + kb + k4);
            uint2 l = *(const uint2*)(wtLo + (size_t)(n0 + row) * Ktot + kb + k4);
            uint32_t sw = SMEM_SWIZZLE_128B((uint32_t)(row * 128 + k4 * 2));
            *(uint2*)(sBh + sw) = h;
            *(uint2*)(sBl + sw) = l;
        }
        __syncthreads();
#pragma unroll
        for (int ks = 0; ks < 4; ks++) {
            uint32_t ah[4], al[4];
            uint32_t aOff = SMEM_SWIZZLE_128B(
                (uint32_t)((wm * 16 + aRow) * 128 + ks * 32 + aKb));
            LDSM_X4(ah[0], ah[1], ah[2], ah[3], aHiA + aOff);
            LDSM_X4(al[0], al[1], al[2], al[3], aLoA + aOff);
            uint32_t bh[4][2], bl[4][2];
#pragma unroll
            for (int np = 0; np < 2; np++) {
                int nb = wn * 32 + np * 16;
                uint32_t bOff = SMEM_SWIZZLE_128B(
                    (uint32_t)((nb + bRow) * 128 + ks * 32 + bKb));
                LDSM_X4(bh[2 * np][0], bh[2 * np][1], bh[2 * np + 1][0], bh[2 * np + 1][1],
                        bHiA + bOff);
                LDSM_X4(bl[2 * np][0], bl[2 * np][1], bl[2 * np + 1][0], bl[2 * np + 1][1],
                        bLoA + bOff);
            }
#pragma unroll
            for (int nt = 0; nt < 4; nt++) {
                mma16816(acc[nt], ah, bh[nt]);
                mma16816(acc[nt], al, bh[nt]);
                mma16816(acc[nt], ah, bl[nt]);
            }
        }
        __syncthreads();
    }

#pragma unroll
    for (int half = 0; half < 2; half++) {
        int r = row0 + wm * 16 + g + half * 8;
        float* Cr = C + (size_t)r * NOUT;
#pragma unroll
        for (int nt = 0; nt < 4; nt++) {
            int col = n0 + wn * 32 + nt * 8 + t4 * 2;
            float v0 = acc[nt][half * 2 + 0];
            float v1 = acc[nt][half * 2 + 1];
            if (MODE >= 1) {
                v0 += bias[col]; v1 += bias[col + 1];
                if (MODE == 1) { v0 = fmaxf(v0, 0.f); v1 = fmaxf(v1, 0.f); }
            }
            *(float2*)(Cr + col) = make_float2(v0, v1);
        }
    }
}

// ---------------- edge aggregation (normalization folded in) ------------------
__global__ void __launch_bounds__(256) k_agg(const float* __restrict__ H,
                                             const float* __restrict__ bsum,
                                             float* __restrict__ out) {
    int v = (blockIdx.x * 256 + threadIdx.x) >> 5;
    int lane = threadIdx.x & 31;
    if (v >= NNODE) return;
    float dv = g_dinv[v];
    float4 zv = *((const float4*)(H + (size_t)v * 128) + lane);
    float4 acc = make_float4(dv * zv.x, dv * zv.y, dv * zv.z, dv * zv.w);  // self loop
    int p = g_rowptr[v], p1 = g_rowptr[v + 1];
    for (; p + 3 < p1; p += 4) {
        int u0 = g_csr[p], u1 = g_csr[p + 1], u2 = g_csr[p + 2], u3 = g_csr[p + 3];
        float d0 = g_dinv[u0], d1 = g_dinv[u1], d2 = g_dinv[u2], d3 = g_dinv[u3];
        float4 z0 = *((const float4*)(H + (size_t)u0 * 128) + lane);
        float4 z1 = *((const float4*)(H + (size_t)u1 * 128) + lane);
        float4 z2 = *((const float4*)(H + (size_t)u2 * 128) + lane);
        float4 z3 = *((const float4*)(H + (size_t)u3 * 128) + lane);
        acc.x += d0 * z0.x + d1 * z1.x + d2 * z2.x + d3 * z3.x;
        acc.y += d0 * z0.y + d1 * z1.y + d2 * z2.y + d3 * z3.y;
        acc.z += d0 * z0.z + d1 * z1.z + d2 * z2.z + d3 * z3.z;
        acc.w += d0 * z0.w + d1 * z1.w + d2 * z2.w + d3 * z3.w;
    }
    for (; p < p1; p++) {
        int u = g_csr[p];
        float du = g_dinv[u];
        float4 z = *((const float4*)(H + (size_t)u * 128) + lane);
        acc.x += du * z.x; acc.y += du * z.y;
        acc.z += du * z.z; acc.w += du * z.w;
    }
    float4 b = *((const float4*)bsum + lane);
    float4 o;
    o.x = fmaxf(dv * acc.x + b.x, 0.f);
    o.y = fmaxf(dv * acc.y + b.y, 0.f);
    o.z = fmaxf(dv * acc.z + b.z, 0.f);
    o.w = fmaxf(dv * acc.w + b.w, 0.f);
    *((float4*)(out + (size_t)v * 128) + lane) = o;
}

// ---------------- host orchestration -----------------------------------------
extern "C" void kernel_launch(void* const* d_in, const int* in_sizes, int n_in,
                              void* d_out, int out_size) {
    const float* x    = (const float*)d_in[0];
    const int*   sub  = (const int*)d_in[1];
    const float* adj  = (const float*)d_in[2];
    const float* gcnW = (const float*)d_in[3];
    const float* gcnB = (const float*)d_in[4];
    const float* W1   = (const float*)d_in[5];
    const float* b1   = (const float*)d_in[6];
    const float* W2   = (const float*)d_in[7];
    const float* b2   = (const float*)d_in[8];
    float* out = (float*)d_out;

    void* p;
    float *pY, *pX, *pS, *pZ, *pA, *pB;
    __nv_bfloat16 *pWLh, *pWLl, *pW1h, *pW1l, *pW2h, *pW2l;
    cudaGetSymbolAddress(&p, g_Y);    pY = (float*)p;
    cudaGetSymbolAddress(&p, g_X);    pX = (float*)p;
    cudaGetSymbolAddress(&p, g_S);    pS = (float*)p;
    cudaGetSymbolAddress(&p, g_Z);    pZ = (float*)p;
    cudaGetSymbolAddress(&p, g_A);    pA = (float*)p;
    cudaGetSymbolAddress(&p, g_bsum); pB = (float*)p;
    cudaGetSymbolAddress(&p, g_WLhi); pWLh = (__nv_bfloat16*)p;
    cudaGetSymbolAddress(&p, g_WLlo); pWLl = (__nv_bfloat16*)p;
    cudaGetSymbolAddress(&p, g_W1hi); pW1h = (__nv_bfloat16*)p;
    cudaGetSymbolAddress(&p, g_W1lo); pW1l = (__nv_bfloat16*)p;
    cudaGetSymbolAddress(&p, g_W2hi); pW2h = (__nv_bfloat16*)p;
    cudaGetSymbolAddress(&p, g_W2lo); pW2l = (__nv_bfloat16*)p;

    // deps of the first k_mma: A powers -> aprep -> wprep0 -> mixmma
    k_copyA<<<16, 256>>>(adj);
    k_mm64<<<1, dim3(64, 16)>>>(pA, pA, pA + 4096);            // A^2
    k_mm64<<<1, dim3(64, 16)>>>(pA + 4096, pA, pA + 2 * 4096); // A^3
    k_aprep<<<48, 256>>>();
    k_wprep<<<(512 * 128 + 255) / 256, 256>>>(gcnW, pWLh, pWLl, 512, 128);
    k_mixmma<<<dim3(2048, 3), 256>>>(x, pY);                    // mix L0 (HMMA)
    k_mma<128, 0><<<dim3(1024, 2), 256>>>(x, pY, pWLh, pWLl, nullptr, pZ, 8);

    // graph preprocessing (needed before first k_agg)
    k_init<<<256, 256>>>();
    k_hist<<<NEDGE / 256, 256>>>(sub + NEDGE);
    k_scan_partial<<<256, 256>>>();
    k_scan_block<<<1, 256>>>();
    k_scan_final<<<256, 256>>>();
    k_fill<<<NEDGE / 256, 256>>>(sub, sub + NEDGE);
    // remaining weight prep
    k_wprep<<<(512 * 128 + 255) / 256, 256>>>(gcnW + 65536, pWLh + 65536, pWLl + 65536, 512, 128);
    k_wprep<<<(512 * 128 + 255) / 256, 256>>>(gcnW + 131072, pWLh + 131072, pWLl + 131072, 512, 128);
    k_wprep<<<(128 * 128 + 255) / 256, 256>>>(W1, pW1h, pW1l, 128, 128);
    k_wprep<<<(128 * 64 + 255) / 256, 256>>>(W2, pW2h, pW2l, 128, 64);
    k_bsum<<<2, 256>>>(gcnB);

    // layer 0 aggregation
    float* bufs[2] = { pX, pS };
    k_agg<<<NNODE / 8, 256>>>(pZ, pB, bufs[0]);
    const float* cur = bufs[0];
    // layers 1..2
    for (int l = 1; l < NLAYER; l++) {
        k_mixmma<<<dim3(2048, 3), 256>>>(cur, pY);
        k_mma<128, 0><<<dim3(1024, 2), 256>>>(cur, pY, pWLh + (size_t)l * 65536,
                                              pWLl + (size_t)l * 65536, nullptr, pZ, 8);
        k_agg<<<NNODE / 8, 256>>>(pZ, pB + l * 128, bufs[l & 1]);
        cur = bufs[l & 1];
    }
    // MLP head
    k_mma<128, 1><<<dim3(1024, 2), 256>>>(cur, nullptr, pW1h, pW1l, b1, pZ, 2);
    k_mma<64, 2><<<dim3(1024, 1), 256>>>(pZ, nullptr, pW2h, pW2l, b2, out, 2);
}

// round 11
// speedup vs baseline: 3.2519x; 1.1223x over previous
#include <cuda_runtime.h>
#include <cuda_bf16.h>
#include <cstdint>

#define NNODE 65536
#define NEDGE 1048576
#define NLAYER 3

// ---------------- scratch (static device globals) ---------------------------
__device__ float g_dinv[NNODE];
__device__ int   g_indeg[NNODE];
__device__ int   g_rowptr[NNODE + 1];
__device__ int   g_cursor[NNODE];
__device__ int   g_csr[NEDGE];
__device__ int   g_part[256];
__device__ float g_A[3][64 * 64];              // [A, A^2, A^3] stacked
__device__ __nv_bfloat16 g_Ahi[3 * 4096], g_Alo[3 * 4096];
__device__ float g_bsum[NLAYER][128];
__device__ float g_Y[(size_t)3 * NNODE * 128]; // mixed features
__device__ float g_X[(size_t)NNODE * 128];
__device__ float g_S[(size_t)NNODE * 128];
__device__ float g_Z[(size_t)NNODE * 128];
// bf16 split weights, transposed to [n][k]
__device__ __nv_bfloat16 g_WLhi[3][128 * 512], g_WLlo[3][128 * 512];
__device__ __nv_bfloat16 g_W1hi[128 * 128],    g_W1lo[128 * 128];
__device__ __nv_bfloat16 g_W2hi[64 * 128],     g_W2lo[64 * 128];

// ================= helpers ====================================================
__device__ __forceinline__ uint32_t smem_to_u32(const void* p) {
    uint32_t a;
    asm("{ .reg .u64 t; cvta.to.shared.u64 t, %1; cvt.u32.u64 %0, t; }" : "=r"(a) : "l"(p));
    return a;
}
#define SMEM_SWIZZLE_128B(o) ((o) ^ (((o) >> 3) & 0x70))

#define LDSM_X4(r0, r1, r2, r3, addr) \
    asm volatile("ldmatrix.sync.aligned.m8n8.x4.shared.b16 {%0,%1,%2,%3}, [%4];" \
                 : "=r"(r0), "=r"(r1), "=r"(r2), "=r"(r3) : "r"(addr))

__device__ __forceinline__ void mma16816(float* c, const uint32_t* a, const uint32_t* b) {
    asm volatile(
        "mma.sync.aligned.m16n8k16.row.col.f32.bf16.bf16.f32 "
        "{%0,%1,%2,%3}, {%4,%5,%6,%7}, {%8,%9}, {%0,%1,%2,%3};"
        : "+f"(c[0]), "+f"(c[1]), "+f"(c[2]), "+f"(c[3])
        : "r"(a[0]), "r"(a[1]), "r"(a[2]), "r"(a[3]), "r"(b[0]), "r"(b[1]));
}

__device__ __forceinline__ void bf16split4(float4 v, uint2& hp, uint2& lp) {
    __nv_bfloat16 h0 = __float2bfloat16(v.x), h1 = __float2bfloat16(v.y);
    __nv_bfloat16 h2 = __float2bfloat16(v.z), h3 = __float2bfloat16(v.w);
    __nv_bfloat16 l0 = __float2bfloat16(v.x - __bfloat162float(h0));
    __nv_bfloat16 l1 = __float2bfloat16(v.y - __bfloat162float(h1));
    __nv_bfloat16 l2 = __float2bfloat16(v.z - __bfloat162float(h2));
    __nv_bfloat16 l3 = __float2bfloat16(v.w - __bfloat162float(h3));
    hp.x = (uint32_t)*(unsigned short*)&h0 | ((uint32_t)*(unsigned short*)&h1 << 16);
    hp.y = (uint32_t)*(unsigned short*)&h2 | ((uint32_t)*(unsigned short*)&h3 << 16);
    lp.x = (uint32_t)*(unsigned short*)&l0 | ((uint32_t)*(unsigned short*)&l1 << 16);
    lp.y = (uint32_t)*(unsigned short*)&l2 | ((uint32_t)*(unsigned short*)&l3 << 16);
}

// ---------------- graph preprocessing ---------------------------------------
__global__ void k_init() {
    int i = blockIdx.x * blockDim.x + threadIdx.x;
    if (i < NNODE) { g_indeg[i] = 0; g_cursor[i] = 0; }
}
__global__ void k_hist(const int* __restrict__ dst) {
    int e = blockIdx.x * blockDim.x + threadIdx.x;
    if (e < NEDGE) atomicAdd(&g_indeg[dst[e]], 1);
}
__global__ void k_scan_partial() {
    __shared__ int sh[256];
    int b = blockIdx.x, t = threadIdx.x;
    sh[t] = g_indeg[b * 256 + t];
    __syncthreads();
    for (int s = 128; s > 0; s >>= 1) {
        if (t < s) sh[t] += sh[t + s];
        __syncthreads();
    }
    if (t == 0) g_part[b] = sh[0];
}
__global__ void k_scan_block() {
    __shared__ int sh[256];
    int t = threadIdx.x;
    int v = g_part[t];
    sh[t] = v;
    __syncthreads();
    for (int off = 1; off < 256; off <<= 1) {
        int xv = (t >= off) ? sh[t - off] : 0;
        __syncthreads();
        sh[t] += xv;
        __syncthreads();
    }
    g_part[t] = sh[t] - v;
}
__global__ void k_scan_final() {
    __shared__ int sh[256];
    int b = blockIdx.x, t = threadIdx.x;
    int v = g_indeg[b * 256 + t];
    sh[t] = v;
    __syncthreads();
    for (int off = 1; off < 256; off <<= 1) {
        int xv = (t >= off) ? sh[t - off] : 0;
        __syncthreads();
        sh[t] += xv;
        __syncthreads();
    }
    int excl = sh[t] - v + g_part[b];
    g_rowptr[b * 256 + t] = excl;
    if (b == 255 && t == 255) g_rowptr[NNODE] = excl + v;
    g_dinv[b * 256 + t] = rsqrtf((float)(v + 1));
}
__global__ void k_fill(const int* __restrict__ src, const int* __restrict__ dst) {
    int e = blockIdx.x * blockDim.x + threadIdx.x;
    if (e < NEDGE) {
        int d = dst[e];
        int p = atomicAdd(&g_cursor[d], 1);
        g_csr[g_rowptr[d] + p] = src[e];
    }
}

// ---------------- fused meta prep: copy + A^2 + A^3 + bf16 split (1 block) ----
__global__ void __launch_bounds__(1024) k_metaprep(const float* __restrict__ adj) {
    float* Af = &g_A[0][0];
    int tid = threadIdx.x;
    for (int i = tid; i < 4096; i += 1024) Af[i] = adj[i];
    __syncthreads();
    {   // A^2 = A @ A
        int c = tid & 63;
        for (int r = tid >> 6; r < 64; r += 16) {
            float s = 0.f;
#pragma unroll 16
            for (int k = 0; k < 64; k++) s += Af[r * 64 + k] * Af[k * 64 + c];
            Af[4096 + r * 64 + c] = s;
        }
    }
    __syncthreads();
    {   // A^3 = A^2 @ A
        int c = tid & 63;
        for (int r = tid >> 6; r < 64; r += 16) {
            float s = 0.f;
#pragma unroll 16
            for (int k = 0; k < 64; k++) s += Af[4096 + r * 64 + k] * Af[k * 64 + c];
            Af[8192 + r * 64 + c] = s;
        }
    }
    __syncthreads();
    for (int i = tid; i < 3 * 4096; i += 1024) {
        float v = Af[i];
        __nv_bfloat16 h = __float2bfloat16(v);
        g_Ahi[i] = h;
        g_Alo[i] = __float2bfloat16(v - __bfloat162float(h));
    }
}
__global__ void k_bsum(const float* __restrict__ gb) {
    int i = blockIdx.x * blockDim.x + threadIdx.x;
    if (i < NLAYER * 128) {
        int l = i / 128, c = i % 128;
        float s = 0.f;
        for (int j = 0; j < 4; j++) s += gb[(l * 4 + j) * 128 + c];
        g_bsum[l][c] = s;
    }
}

// weight prep: W[K x N] -> Wt_hi/lo[n][k] bf16 split
__global__ void k_wprep(const float* __restrict__ W, __nv_bfloat16* __restrict__ hi,
                        __nv_bfloat16* __restrict__ lo, int K, int N) {
    int idx = blockIdx.x * 256 + threadIdx.x;
    if (idx >= K * N) return;
    int n = idx / K, k = idx % K;
    float v = W[(size_t)k * N + n];
    __nv_bfloat16 h = __float2bfloat16(v);
    hi[idx] = h;
    lo[idx] = __float2bfloat16(v - __bfloat162float(h));
}

// ---------------- HMMA mix: Y_i[64 x 131072] = A_i[64x64] @ X[64x131072] ------
// grid (2048, 3), block 256. X tile transposed through a padded fp32 smem stage
// (conflict-free both directions), then packed uint2 stores like the A-fill.
__global__ void __launch_bounds__(256) k_mixmma(const float* __restrict__ X,
                                                float* __restrict__ Y) {
    __shared__ __align__(1024) unsigned char sAh[8192];   // 64 n-rows x 64 bf16
    __shared__ __align__(1024) unsigned char sAl[8192];
    __shared__ __align__(1024) unsigned char sXh[8192];   // 64 col-rows x 64(j) bf16
    __shared__ __align__(1024) unsigned char sXl[8192];
    __shared__ float sStage[32][65];                      // transpose stage
    const uint32_t aHiA = smem_to_u32(sAh), aLoA = smem_to_u32(sAl);
    const uint32_t xHiA = smem_to_u32(sXh), xLoA = smem_to_u32(sXl);
    int tid = threadIdx.x, lane = tid & 31, wid = tid >> 5;
    int wm = wid & 3, wn = wid >> 2;
    int i = blockIdx.y;
    int col0 = blockIdx.x * 64;
    int g = lane >> 2, t4 = lane & 3;
    int aRow = lane & 15, aKb = (lane >> 4) * 16;
    int bRow = ((lane >> 4) << 3) + (lane & 7);
    int bKb  = ((lane >> 3) & 1) * 16;

    // load A_i (pre-split bf16): FULL 64x16 uint2 tile
#pragma unroll
    for (int q = 0; q < 4; q++) {
        int idx = tid + 256 * q;               // 0..1023
        int row = idx >> 4, k4 = (idx & 15) * 4;
        uint2 h = *(const uint2*)(g_Ahi + i * 4096 + row * 64 + k4);
        uint2 l = *(const uint2*)(g_Alo + i * 4096 + row * 64 + k4);
        uint32_t sw = SMEM_SWIZZLE_128B((uint32_t)(row * 128 + k4 * 2));
        *(uint2*)(sAh + sw) = h;
        *(uint2*)(sAl + sw) = l;
    }
    // X tile 64(j) x 64(col): stage 32 j-rows at a time in padded fp32,
    // then write transposed [col][j] bf16 as packed uint2 (4 j's per store).
#pragma unroll
    for (int hh = 0; hh < 2; hh++) {
#pragma unroll
        for (int q = 0; q < 2; q++) {
            int idx = tid + 256 * q;           // 0..511
            int jj = idx >> 4, c4 = (idx & 15) * 4;
            float4 v = *(const float4*)(X + (size_t)(hh * 32 + jj) * 131072 + col0 + c4);
            sStage[jj][c4 + 0] = v.x; sStage[jj][c4 + 1] = v.y;
            sStage[jj][c4 + 2] = v.z; sStage[jj][c4 + 3] = v.w;
        }
        __syncthreads();
#pragma unroll
        for (int q = 0; q < 2; q++) {
            int idx = tid + 256 * q;           // 0..511
            int col = idx & 63, j4 = idx >> 6; // j4 0..7
            float4 v = make_float4(sStage[j4 * 4 + 0][col], sStage[j4 * 4 + 1][col],
                                   sStage[j4 * 4 + 2][col], sStage[j4 * 4 + 3][col]);
            uint2 hp, lp;
            bf16split4(v, hp, lp);
            uint32_t sw = SMEM_SWIZZLE_128B((uint32_t)(col * 128 + (hh * 32 + j4 * 4) * 2));
            *(uint2*)(sXh + sw) = hp;
            *(uint2*)(sXl + sw) = lp;
        }
        __syncthreads();
    }

    float acc[4][4] = {};
#pragma unroll
    for (int ks = 0; ks < 4; ks++) {
        uint32_t ah[4], al[4];
        uint32_t aOff = SMEM_SWIZZLE_128B(
            (uint32_t)((wm * 16 + aRow) * 128 + ks * 32 + aKb));
        LDSM_X4(ah[0], ah[1], ah[2], ah[3], aHiA + aOff);
        LDSM_X4(al[0], al[1], al[2], al[3], aLoA + aOff);
        uint32_t bh[4][2], bl[4][2];
#pragma unroll
        for (int np = 0; np < 2; np++) {
            int nb = wn * 32 + np * 16;
            uint32_t bOff = SMEM_SWIZZLE_128B(
                (uint32_t)((nb + bRow) * 128 + ks * 32 + bKb));
            LDSM_X4(bh[2 * np][0], bh[2 * np][1], bh[2 * np + 1][0], bh[2 * np + 1][1],
                    xHiA + bOff);
            LDSM_X4(bl[2 * np][0], bl[2 * np][1], bl[2 * np + 1][0], bl[2 * np + 1][1],
                    xLoA + bOff);
        }
#pragma unroll
        for (int nt = 0; nt < 4; nt++) {
            mma16816(acc[nt], ah, bh[nt]);
            mma16816(acc[nt], al, bh[nt]);
            mma16816(acc[nt], ah, bl[nt]);
        }
    }

    float* Yi = Y + (size_t)i * NNODE * 128;
#pragma unroll
    for (int half = 0; half < 2; half++) {
        int r = wm * 16 + g + half * 8;        // meta-node row n
        float* Yr = Yi + (size_t)r * 131072;
#pragma unroll
        for (int nt = 0; nt < 4; nt++) {
            int col = col0 + wn * 32 + nt * 8 + t4 * 2;
            *(float2*)(Yr + col) = make_float2(acc[nt][half * 2 + 0],
                                               acc[nt][half * 2 + 1]);
        }
    }
}

// ---------------- mma.sync node GEMM (STATIC smem, 64x64 tile) ----------------
// C[65536 x NOUT] = Acat[65536 x (nChunks*64)] @ Wt^T (bf16 2-term split, 3 products)
// grid = (1024, NOUT/64). MODE 0: raw H; MODE 1: relu(+bias); MODE 2: +bias.
template <int NOUT, int MODE>
__global__ void __launch_bounds__(256) k_mma(
    const float* __restrict__ A0, const float* __restrict__ A1,
    const __nv_bfloat16* __restrict__ wtHi, const __nv_bfloat16* __restrict__ wtLo,
    const float* __restrict__ bias, float* __restrict__ C, int nChunks)
{
    __shared__ __align__(1024) unsigned char sAh[8192];
    __shared__ __align__(1024) unsigned char sAl[8192];
    __shared__ __align__(1024) unsigned char sBh[8192];
    __shared__ __align__(1024) unsigned char sBl[8192];
    const uint32_t aHiA = smem_to_u32(sAh), aLoA = smem_to_u32(sAl);
    const uint32_t bHiA = smem_to_u32(sBh), bLoA = smem_to_u32(sBl);
    int tid = threadIdx.x, lane = tid & 31, wid = tid >> 5;
    int wm = wid & 3, wn = wid >> 2;
    int row0 = blockIdx.x * 64;
    int n0   = blockIdx.y * 64;
    int Ktot = nChunks * 64;
    int g = lane >> 2, t4 = lane & 3;
    int aRow = lane & 15;
    int aKb  = (lane >> 4) * 16;
    int bRow = ((lane >> 4) << 3) + (lane & 7);
    int bKb  = ((lane >> 3) & 1) * 16;

    float acc[4][4] = {};

    for (int c = 0; c < nChunks; c++) {
        const float* S;
        int kk;
        if (c < 2) { S = A0; kk = c * 64; }
        else { S = A1 + (size_t)((c - 2) >> 1) * ((size_t)NNODE * 128); kk = (c & 1) * 64; }
        const int kb = c * 64;
        const float* ap = S + (size_t)row0 * 128 + kk;
#pragma unroll
        for (int q = 0; q < 4; q++) {
            int idx = tid + 256 * q;
            int row = idx >> 4, k4 = (idx & 15) * 4;
            float4 v = *(const float4*)(ap + (size_t)row * 128 + k4);
            uint2 hp, lp;
            bf16split4(v, hp, lp);
            uint32_t sw = SMEM_SWIZZLE_128B((uint32_t)(row * 128 + k4 * 2));
            *(uint2*)(sAh + sw) = hp;
            *(uint2*)(sAl + sw) = lp;
        }
#pragma unroll
        for (int q = 0; q < 4; q++) {
            int idx = tid + 256 * q;
            int row = idx >> 4, k4 = (idx & 15) * 4;
            uint2 h = *(const uint2*)(wtHi + (size_t)(n0 + row) * Ktot + kb + k4);
            uint2 l = *(const uint2*)(wtLo + (size_t)(n0 + row) * Ktot + kb + k4);
            uint32_t sw = SMEM_SWIZZLE_128B((uint32_t)(row * 128 + k4 * 2));
            *(uint2*)(sBh + sw) = h;
            *(uint2*)(sBl + sw) = l;
        }
        __syncthreads();
#pragma unroll
        for (int ks = 0; ks < 4; ks++) {
            uint32_t ah[4], al[4];
            uint32_t aOff = SMEM_SWIZZLE_128B(
                (uint32_t)((wm * 16 + aRow) * 128 + ks * 32 + aKb));
            LDSM_X4(ah[0], ah[1], ah[2], ah[3], aHiA + aOff);
            LDSM_X4(al[0], al[1], al[2], al[3], aLoA + aOff);
            uint32_t bh[4][2], bl[4][2];
#pragma unroll
            for (int np = 0; np < 2; np++) {
                int nb = wn * 32 + np * 16;
                uint32_t bOff = SMEM_SWIZZLE_128B(
                    (uint32_t)((nb + bRow) * 128 + ks * 32 + bKb));
                LDSM_X4(bh[2 * np][0], bh[2 * np][1], bh[2 * np + 1][0], bh[2 * np + 1][1],
                        bHiA + bOff);
                LDSM_X4(bl[2 * np][0], bl[2 * np][1], bl[2 * np + 1][0], bl[2 * np + 1][1],
                        bLoA + bOff);
            }
#pragma unroll
            for (int nt = 0; nt < 4; nt++) {
                mma16816(acc[nt], ah, bh[nt]);
                mma16816(acc[nt], al, bh[nt]);
                mma16816(acc[nt], ah, bl[nt]);
            }
        }
        __syncthreads();
    }

#pragma unroll
    for (int half = 0; half < 2; half++) {
        int r = row0 + wm * 16 + g + half * 8;
        float* Cr = C + (size_t)r * NOUT;
#pragma unroll
        for (int nt = 0; nt < 4; nt++) {
            int col = n0 + wn * 32 + nt * 8 + t4 * 2;
            float v0 = acc[nt][half * 2 + 0];
            float v1 = acc[nt][half * 2 + 1];
            if (MODE >= 1) {
                v0 += bias[col]; v1 += bias[col + 1];
                if (MODE == 1) { v0 = fmaxf(v0, 0.f); v1 = fmaxf(v1, 0.f); }
            }
            *(float2*)(Cr + col) = make_float2(v0, v1);
        }
    }
}

// ---------------- edge aggregation (normalization folded in) ------------------
__global__ void __launch_bounds__(256) k_agg(const float* __restrict__ H,
                                             const float* __restrict__ bsum,
                                             float* __restrict__ out) {
    int v = (blockIdx.x * 256 + threadIdx.x) >> 5;
    int lane = threadIdx.x & 31;
    if (v >= NNODE) return;
    float dv = g_dinv[v];
    float4 zv = *((const float4*)(H + (size_t)v * 128) + lane);
    float4 acc = make_float4(dv * zv.x, dv * zv.y, dv * zv.z, dv * zv.w);  // self loop
    int p = g_rowptr[v], p1 = g_rowptr[v + 1];
    for (; p + 3 < p1; p += 4) {
        int u0 = g_csr[p], u1 = g_csr[p + 1], u2 = g_csr[p + 2], u3 = g_csr[p + 3];
        float d0 = g_dinv[u0], d1 = g_dinv[u1], d2 = g_dinv[u2], d3 = g_dinv[u3];
        float4 z0 = *((const float4*)(H + (size_t)u0 * 128) + lane);
        float4 z1 = *((const float4*)(H + (size_t)u1 * 128) + lane);
        float4 z2 = *((const float4*)(H + (size_t)u2 * 128) + lane);
        float4 z3 = *((const float4*)(H + (size_t)u3 * 128) + lane);
        acc.x += d0 * z0.x + d1 * z1.x + d2 * z2.x + d3 * z3.x;
        acc.y += d0 * z0.y + d1 * z1.y + d2 * z2.y + d3 * z3.y;
        acc.z += d0 * z0.z + d1 * z1.z + d2 * z2.z + d3 * z3.z;
        acc.w += d0 * z0.w + d1 * z1.w + d2 * z2.w + d3 * z3.w;
    }
    for (; p < p1; p++) {
        int u = g_csr[p];
        float du = g_dinv[u];
        float4 z = *((const float4*)(H + (size_t)u * 128) + lane);
        acc.x += du * z.x; acc.y += du * z.y;
        acc.z += du * z.z; acc.w += du * z.w;
    }
    float4 b = *((const float4*)bsum + lane);
    float4 o;
    o.x = fmaxf(dv * acc.x + b.x, 0.f);
    o.y = fmaxf(dv * acc.y + b.y, 0.f);
    o.z = fmaxf(dv * acc.z + b.z, 0.f);
    o.w = fmaxf(dv * acc.w + b.w, 0.f);
    *((float4*)(out + (size_t)v * 128) + lane) = o;
}

// ---------------- host orchestration -----------------------------------------
extern "C" void kernel_launch(void* const* d_in, const int* in_sizes, int n_in,
                              void* d_out, int out_size) {
    const float* x    = (const float*)d_in[0];
    const int*   sub  = (const int*)d_in[1];
    const float* adj  = (const float*)d_in[2];
    const float* gcnW = (const float*)d_in[3];
    const float* gcnB = (const float*)d_in[4];
    const float* W1   = (const float*)d_in[5];
    const float* b1   = (const float*)d_in[6];
    const float* W2   = (const float*)d_in[7];
    const float* b2   = (const float*)d_in[8];
    float* out = (float*)d_out;

    void* p;
    float *pY, *pX, *pS, *pZ, *pB;
    __nv_bfloat16 *pWLh, *pWLl, *pW1h, *pW1l, *pW2h, *pW2l;
    cudaGetSymbolAddress(&p, g_Y);    pY = (float*)p;
    cudaGetSymbolAddress(&p, g_X);    pX = (float*)p;
    cudaGetSymbolAddress(&p, g_S);    pS = (float*)p;
    cudaGetSymbolAddress(&p, g_Z);    pZ = (float*)p;
    cudaGetSymbolAddress(&p, g_bsum); pB = (float*)p;
    cudaGetSymbolAddress(&p, g_WLhi); pWLh = (__nv_bfloat16*)p;
    cudaGetSymbolAddress(&p, g_WLlo); pWLl = (__nv_bfloat16*)p;
    cudaGetSymbolAddress(&p, g_W1hi); pW1h = (__nv_bfloat16*)p;
    cudaGetSymbolAddress(&p, g_W1lo); pW1l = (__nv_bfloat16*)p;
    cudaGetSymbolAddress(&p, g_W2hi); pW2h = (__nv_bfloat16*)p;
    cudaGetSymbolAddress(&p, g_W2lo); pW2l = (__nv_bfloat16*)p;

    // launches 1-3 are the deps of k_mma layer 0; k_mma lands in profiled slot 4
    k_metaprep<<<1, 1024>>>(adj);                                           // 1
    k_wprep<<<(512 * 128 + 255) / 256, 256>>>(gcnW, pWLh, pWLl, 512, 128);  // 2
    k_mixmma<<<dim3(2048, 3), 256>>>(x, pY);                                // 3
    k_mma<128, 0><<<dim3(1024, 2), 256>>>(x, pY, pWLh, pWLl, nullptr, pZ, 8); // 4 <- ncu

    // graph preprocessing (needed before first k_agg)
    k_init<<<256, 256>>>();
    k_hist<<<NEDGE / 256, 256>>>(sub + NEDGE);
    k_scan_partial<<<256, 256>>>();
    k_scan_block<<<1, 256>>>();
    k_scan_final<<<256, 256>>>();
    k_fill<<<NEDGE / 256, 256>>>(sub, sub + NEDGE);
    // remaining weight prep
    k_wprep<<<(512 * 128 + 255) / 256, 256>>>(gcnW + 65536, pWLh + 65536, pWLl + 65536, 512, 128);
    k_wprep<<<(512 * 128 + 255) / 256, 256>>>(gcnW + 131072, pWLh + 131072, pWLl + 131072, 512, 128);
    k_wprep<<<(128 * 128 + 255) / 256, 256>>>(W1, pW1h, pW1l, 128, 128);
    k_wprep<<<(128 * 64 + 255) / 256, 256>>>(W2, pW2h, pW2l, 128, 64);
    k_bsum<<<2, 256>>>(gcnB);

    // layer 0 aggregation
    float* bufs[2] = { pX, pS };
    k_agg<<<NNODE / 8, 256>>>(pZ, pB, bufs[0]);
    const float* cur = bufs[0];
    // layers 1..2
    for (int l = 1; l < NLAYER; l++) {
        k_mixmma<<<dim3(2048, 3), 256>>>(cur, pY);
        k_mma<128, 0><<<dim3(1024, 2), 256>>>(cur, pY, pWLh + (size_t)l * 65536,
                                              pWLl + (size_t)l * 65536, nullptr, pZ, 8);
        k_agg<<<NNODE / 8, 256>>>(pZ, pB + l * 128, bufs[l & 1]);
        cur = bufs[l & 1];
    }
    // MLP head
    k_mma<128, 1><<<dim3(1024, 2), 256>>>(cur, nullptr, pW1h, pW1l, b1, pZ, 2);
    k_mma<64, 2><<<dim3(1024, 1), 256>>>(pZ, nullptr, pW2h, pW2l, b2, out, 2);
}